// round 9
// baseline (speedup 1.0000x reference)
#include <cuda_runtime.h>
#include <cstdint>
#include <math_constants.h>

#define NN 20000
#define NE 320000
#define BFDIM 128
#define FD 64
#define RD 32
#define KSEL 160000
#define NITER 4
#define SB 148
#define STH 1024

typedef unsigned long long ull;

// ---------------- scratch ----------------
__device__ __align__(16) float g_rel[RD * BFDIM];
__device__ __align__(16) float g_wa[4 * BFDIM];
__device__ float g_drel[4 * RD];
__device__ float g_wsumT[FD * FD];
__device__ float g_w2T[FD * FD];
__device__ float g_tr[BFDIM];
__device__ float g_rsum[BFDIM];
__device__ float g_nx[NN];
__device__ __align__(16) float g_aN[NE];
__device__ __align__(16) float g_xbuf[NN * BFDIM];   // double buffer (odd iters)
__device__ __align__(16) unsigned g_hist[65536];
__device__ __align__(16) unsigned g_coarse[256];
__device__ unsigned g_cnt1;
__device__ unsigned g_cnt2;
__device__ unsigned g_flagA;
__device__ unsigned g_d0;
__device__ long long g_rem0;
__device__ unsigned g_eqCount;
__device__ int g_eqE[32768];
__device__ unsigned g_eqB[32768];
__device__ ull g_thresh;
// CSR
__device__ int g_srcPtr[NN + 1];
__device__ int g_dstPtr[NN + 1];
__device__ unsigned g_srcCnt[NN];
__device__ unsigned g_dstCnt[NN];
__device__ unsigned g_srcPk[NE];           // e | (r<<19), ordered by src
__device__ __align__(8) uint2 g_dstPk[NE]; // {e, s|(r<<16)}, ordered by dst

// ---------------- prep1: weights + csr count (merged grid) ----------------
__global__ __launch_bounds__(256) void k_prep1(const float* __restrict__ q,
                                               const float* __restrict__ rw,
                                               const float* __restrict__ rb,
                                               const float* __restrict__ Wm,
                                               const float* __restrict__ av,
                                               const float* __restrict__ lw,
                                               const int* __restrict__ ei) {
    if (blockIdx.x < 34) {
        int t = blockIdx.x * blockDim.x + threadIdx.x;
        if (t < 4096) {
            int b = t >> 11, j = t & 2047;
            const float* qr = q + b * FD;
            const float* wr = rw + j * FD;
            float s = rb[j];
#pragma unroll 16
            for (int k = 0; k < FD; k++) s += qr[k] * wr[k];
            g_rel[b * (RD * FD) + j] = s;
        } else if (t < 4608) {
            int u = t - 4096;
            int i = u >> 7, j = u & 127;
            float s = 0.f;
#pragma unroll 16
            for (int f = 0; f < FD; f++) s += Wm[j * FD + f] * av[i * FD + f];
            g_wa[u] = s;
        } else if (t < 8704) {
            int u = t - 4608;
            int j = u >> 6, f = u & 63;
            float w2 = lw[f * 2 * FD + FD + j];
            g_w2T[j * FD + f] = w2;
            g_wsumT[j * FD + f] = lw[f * 2 * FD + j] + w2;
        }
    } else {
        int e = (blockIdx.x - 34) * blockDim.x + threadIdx.x;
        if (e < NE) {
            atomicAdd(&g_srcCnt[ei[e]], 1u);
            atomicAdd(&g_dstCnt[ei[NE + e]], 1u);
        }
    }
}

__global__ __launch_bounds__(1024) void k_csr_scan() {
    __shared__ unsigned ss[1024];
    int t = threadIdx.x;
    if (t < 4 * RD) {
        int i = t >> 5, r = t & 31;
        float s = 0.f;
#pragma unroll 16
        for (int j = 0; j < BFDIM; j++) s += g_rel[r * BFDIM + j] * g_wa[i * BFDIM + j];
        g_drel[t] = s;
    }
    for (int phase = 0; phase < 2; ++phase) {
        unsigned* cnt = phase ? g_dstCnt : g_srcCnt;
        int* ptr = phase ? g_dstPtr : g_srcPtr;
        unsigned loc[20]; unsigned s = 0;
#pragma unroll
        for (int i = 0; i < 20; i++) {
            int idx = t * 20 + i;
            unsigned v = (idx < NN) ? cnt[idx] : 0u;
            loc[i] = s; s += v;
        }
        ss[t] = s;
        __syncthreads();
        for (int off = 1; off < 1024; off <<= 1) {
            unsigned v = (t >= off) ? ss[t - off] : 0u;
            __syncthreads();
            ss[t] += v;
            __syncthreads();
        }
        unsigned base = (t > 0) ? ss[t - 1] : 0u;
#pragma unroll
        for (int i = 0; i < 20; i++) {
            int idx = t * 20 + i;
            if (idx < NN) { ptr[idx] = (int)(base + loc[i]); cnt[idx] = 0u; }
        }
        if (t == 0) ptr[NN] = NE;
        __syncthreads();
    }
}

// ---------------- csr fill + init (merged grid) ----------------
__global__ __launch_bounds__(256) void k_fill_init(const int* __restrict__ ei,
                                                   const int* __restrict__ ri,
                                                   const float* __restrict__ bnd,
                                                   float* __restrict__ x) {
    int tid = threadIdx.x;
    if (blockIdx.x < 1250) {
        int e = blockIdx.x * 256 + tid;
        if (e >= NE) return;
        int s = ei[e];
        unsigned r = (unsigned)ri[e];
        unsigned p = atomicAdd(&g_srcCnt[s], 1u);
        g_srcPk[g_srcPtr[s] + (int)p] = (unsigned)e | (r << 19);
        int d = ei[NE + e];
        unsigned p2 = atomicAdd(&g_dstCnt[d], 1u);
        g_dstPk[g_dstPtr[d] + (int)p2] = make_uint2((unsigned)e, (unsigned)s | (r << 16));
    } else {
        __shared__ float racc[BFDIM];
        if (tid < BFDIM) racc[tid] = 0.f;
        __syncthreads();
        int warp = ((blockIdx.x - 1250) * 256 + tid) >> 5;
        int l = tid & 31;
        if (warp < NN) {
            float4 v = reinterpret_cast<const float4*>(bnd)[(size_t)warp * 32 + l];
            reinterpret_cast<float4*>(x)[(size_t)warp * 32 + l] = v;
            float4 w = reinterpret_cast<const float4*>(g_wa)[l];
            float s = v.x * w.x + v.y * w.y + v.z * w.z + v.w * w.w;
#pragma unroll
            for (int o = 16; o; o >>= 1) s += __shfl_xor_sync(0xffffffffu, s, o);
            if (l == 0) g_nx[warp] = s;
            atomicAdd(&racc[l * 4 + 0], v.x);
            atomicAdd(&racc[l * 4 + 1], v.y);
            atomicAdd(&racc[l * 4 + 2], v.z);
            atomicAdd(&racc[l * 4 + 3], v.w);
        }
        __syncthreads();
        if (tid < BFDIM) atomicAdd(&g_rsum[tid], racc[tid]);
    }
}

// ---------------- descending 256-bin pick helper ----------------
__device__ __forceinline__ void pick_desc(unsigned* h, unsigned* sc, int t, long long R,
                                          unsigned* outDigit, long long* outRem) {
    if (t < 256) sc[t] = h[255 - t];
    __syncthreads();
    for (int off = 1; off < 256; off <<= 1) {
        unsigned v = (t < 256 && t >= off) ? sc[t - off] : 0u;
        __syncthreads();
        if (t < 256) sc[t] += v;
        __syncthreads();
    }
    if (t < 256) {
        long long incl = (long long)sc[t];
        long long before = incl - (long long)h[255 - t];
        if (before < R && R <= incl) { *outDigit = (unsigned)(255 - t); *outRem = R - before; }
    }
    __syncthreads();
}

// ==== persistent fused: softmax + hist + pick + collect + resolve + tr ====
__global__ __launch_bounds__(STH) void k_soft(int it, const float* __restrict__ trw,
                                              const float* __restrict__ trb) {
    extern __shared__ unsigned sh[];   // 32768 words packed hist
    __shared__ unsigned hh[256], hsc[256];
    __shared__ unsigned selDigit; __shared__ long long selRem;
    __shared__ unsigned isLast1, isLast2, candCnt;
    __shared__ int cand[4096];
    int tid = threadIdx.x;
    for (int i = tid; i < 32768; i += STH) sh[i] = 0u;
    __syncthreads();
    int l16 = tid & 15;
    unsigned hmask = ((tid & 16) ? 0xFFFF0000u : 0x0000FFFFu);
    int grp = blockIdx.x * (STH / 16) + (tid >> 4);
    int totalGrp = SB * (STH / 16);
    const float* drel = g_drel + it * RD;
    for (int n = grp; n < NN; n += totalGrp) {
        int beg = g_srcPtr[n], end = g_srcPtr[n + 1];
        if (beg == end) continue;
        float nx = g_nx[n];
        float tc[4]; unsigned pkc[4];
        float m = -CUDART_INF_F;
        int k0 = beg + l16;
#pragma unroll
        for (int u = 0; u < 4; ++u) {
            int kk = k0 + u * 16;
            float t = -CUDART_INF_F; unsigned pk = 0u;
            if (kk < end) {
                pk = g_srcPk[kk];
                t = nx + drel[pk >> 19];
                t = t > 0.f ? t : 0.2f * t;
            }
            tc[u] = t; pkc[u] = pk;
            m = fmaxf(m, t);
        }
        for (int kk = k0 + 64; kk < end; kk += 16) {
            unsigned pk = g_srcPk[kk];
            float t = nx + drel[pk >> 19];
            t = t > 0.f ? t : 0.2f * t;
            m = fmaxf(m, t);
        }
#pragma unroll
        for (int o = 8; o; o >>= 1) m = fmaxf(m, __shfl_xor_sync(hmask, m, o));
        float sum = 0.f;
#pragma unroll
        for (int u = 0; u < 4; ++u) {
            if (k0 + u * 16 < end) {
                float ex = expf(tc[u] - m);
                tc[u] = ex;            // cache exp value
                sum += ex;
            }
        }
        for (int kk = k0 + 64; kk < end; kk += 16) {
            unsigned pk = g_srcPk[kk];
            float t = nx + drel[pk >> 19];
            t = t > 0.f ? t : 0.2f * t;
            sum += expf(t - m);
        }
#pragma unroll
        for (int o = 8; o; o >>= 1) sum += __shfl_xor_sync(hmask, sum, o);
        float invd = 1.f / (sum + 1e-16f);
#pragma unroll
        for (int u = 0; u < 4; ++u) {
            if (k0 + u * 16 < end) {
                float a = tc[u] * invd;
                g_aN[pkc[u] & 0x7FFFFu] = a;
                unsigned d = __float_as_uint(a) >> 16;
                atomicAdd(&sh[d >> 1], (d & 1) ? 65536u : 1u);
            }
        }
        for (int kk = k0 + 64; kk < end; kk += 16) {
            unsigned pk = g_srcPk[kk];
            float t = nx + drel[pk >> 19];
            t = t > 0.f ? t : 0.2f * t;
            float a = expf(t - m) * invd;
            g_aN[pk & 0x7FFFFu] = a;
            unsigned d = __float_as_uint(a) >> 16;
            atomicAdd(&sh[d >> 1], (d & 1) ? 65536u : 1u);
        }
    }
    __syncthreads();
    // merge packed smem hist -> global fine + coarse
    {
        int w = tid >> 5, l = tid & 31;
        for (int g = w; g < 256; g += (STH / 32)) {
            unsigned gsum = 0;
            int base = g * 128;
#pragma unroll
            for (int j = 0; j < 4; ++j) {
                int wi = base + j * 32 + l;
                unsigned word = sh[wi];
                if (word) {
                    unsigned lo = word & 0xFFFFu, hi = word >> 16;
                    if (lo) atomicAdd(&g_hist[2 * wi], lo);
                    if (hi) atomicAdd(&g_hist[2 * wi + 1], hi);
                    gsum += lo + hi;
                }
            }
#pragma unroll
            for (int o = 16; o; o >>= 1) gsum += __shfl_xor_sync(0xffffffffu, gsum, o);
            if (l == 0 && gsum) atomicAdd(&g_coarse[g], gsum);
        }
    }
    __threadfence();
    if (tid == 0) isLast1 = (atomicAdd(&g_cnt1, 1u) == gridDim.x - 1u) ? 1u : 0u;
    __syncthreads();
    if (isLast1) {
        if (tid < 256) hh[tid] = g_coarse[tid];
        __syncthreads();
        pick_desc(hh, hsc, tid, (long long)KSEL, &selDigit, &selRem);
        unsigned grpd = selDigit; long long R1 = selRem;
        if (tid < 256) hh[tid] = g_hist[grpd * 256 + tid];
        __syncthreads();
        pick_desc(hh, hsc, tid, R1, &selDigit, &selRem);
        if (tid == 0) {
            g_d0 = (grpd << 8) | selDigit;
            g_rem0 = selRem;
            g_eqCount = 0u;
        }
        __syncthreads();
        uint4 z = make_uint4(0u, 0u, 0u, 0u);
        uint4* H = reinterpret_cast<uint4*>(g_hist);
        for (int i = tid; i < 16384; i += STH) H[i] = z;
        if (tid < 64) reinterpret_cast<uint4*>(g_coarse)[tid] = z;
        __threadfence();
        __syncthreads();
        if (tid == 0) atomicExch(&g_flagA, 1u);
    } else {
        if (tid == 0) { while (atomicAdd(&g_flagA, 0u) == 0u) { __nanosleep(64); } }
        __syncthreads();
        __threadfence();
    }
    // ---- all blocks: parallel collect of bucket d0 ----
    {
        unsigned d0 = g_d0;
        const float4* aN4 = reinterpret_cast<const float4*>(g_aN);
        int stride = gridDim.x * STH;
        for (int i = blockIdx.x * STH + tid; i < NE / 4; i += stride) {
            float4 v = aN4[i];
            const float* vf = (const float*)&v;
#pragma unroll
            for (int c = 0; c < 4; ++c) {
                unsigned bits = __float_as_uint(vf[c]);
                if ((bits >> 16) == d0) {
                    unsigned p = atomicAdd(&g_eqCount, 1u);
                    if (p < 32768u) { g_eqE[p] = 4 * i + c; g_eqB[p] = bits; }
                }
            }
        }
    }
    __threadfence();
    if (tid == 0) isLast2 = (atomicAdd(&g_cnt2, 1u) == gridDim.x - 1u) ? 1u : 0u;
    __syncthreads();
    if (!isLast2) return;
    // ---- last block: resolve + tr vector ----
    {
        int c = (int)min(g_eqCount, 32768u);
        long long r0 = g_rem0;
        unsigned d0 = g_d0;
        if (tid < 256) hh[tid] = 0u;
        __syncthreads();
        for (int i = tid; i < c; i += STH) atomicAdd(&hh[(g_eqB[i] >> 8) & 0xFFu], 1u);
        __syncthreads();
        pick_desc(hh, hsc, tid, r0, &selDigit, &selRem);
        unsigned b1 = selDigit; long long r1 = selRem;
        if (tid < 256) hh[tid] = 0u;
        __syncthreads();
        for (int i = tid; i < c; i += STH) {
            unsigned bits = g_eqB[i];
            if (((bits >> 8) & 0xFFu) == b1) atomicAdd(&hh[bits & 0xFFu], 1u);
        }
        __syncthreads();
        pick_desc(hh, hsc, tid, r1, &selDigit, &selRem);
        unsigned T = (d0 << 16) | (b1 << 8) | selDigit;
        int r2 = (int)selRem;
        if (tid == 0) candCnt = 0u;
        __syncthreads();
        for (int i = tid; i < c; i += STH) {
            if (g_eqB[i] == T) {
                unsigned p = atomicAdd(&candCnt, 1u);
                if (p < 4096u) cand[p] = g_eqE[i];
            }
        }
        __syncthreads();
        int tc2 = (int)min(candCnt, 4096u);
        for (int i = tid; i < tc2; i += STH) {
            int e = cand[i];
            int cnt = 0;
            for (int j = 0; j < tc2; ++j) cnt += (cand[j] < e) ? 1 : 0;
            if (cnt == r2 - 1)
                g_thresh = ((ull)T << 32) | (unsigned)(0xFFFFFFFFu - (unsigned)e);
        }
        // trans-readout vector (rsum is complete from previous epi/init)
        float trv = 0.f;
        if (tid < BFDIM) {
            int b = tid >> 6, f = tid & 63;
            const float* r = g_rsum + b * FD;
            float s = trb[f];
            const float inv = 1.f / (float)NN;
#pragma unroll 16
            for (int j = 0; j < FD; j++) s += (r[j] * inv) * trw[f * FD + j];
            trv = s;
        }
        __syncthreads();
        if (tid < BFDIM) { g_tr[tid] = trv; g_rsum[tid] = 0.f; }
        __syncthreads();
        if (tid == 0) { g_cnt1 = 0u; g_cnt2 = 0u; g_flagA = 0u; }
    }
}

// ====== fused scatter + epi: 512 thr, 32 nodes/block, double-buffered x ======
__global__ __launch_bounds__(512) void k_scat_epi(const float* __restrict__ xo,
                                                  float* __restrict__ xn,
                                                  const float* __restrict__ lb,
                                                  const float* __restrict__ lng,
                                                  const float* __restrict__ lnb,
                                                  int it) {
    __shared__ float sWs[FD * FD];
    __shared__ float sW2[FD * FD];
    __shared__ float sTr[BFDIM];
    __shared__ float sWa[BFDIM];
    __shared__ float racc[BFDIM];
    __shared__ float sLb[FD], sG[FD], sB[FD];
    __shared__ float4 sX[32][32];
    __shared__ float4 sS[32][32];
    int tid = threadIdx.x;
    for (int i = tid; i < FD * FD; i += 512) { sWs[i] = g_wsumT[i]; sW2[i] = g_w2T[i]; }
    if (tid < BFDIM) {
        sTr[tid] = g_tr[tid];
        sWa[tid] = (it < 3) ? g_wa[(it + 1) * BFDIM + tid] : 0.f;
        racc[tid] = 0.f;
    }
    if (tid < FD) { sLb[tid] = lb[tid]; sG[tid] = lng[tid]; sB[tid] = lnb[tid]; }
    int w = tid >> 5, l = tid & 31;
    int nbase = blockIdx.x * 32 + w * 2;
    int row0 = w * 2, row1 = w * 2 + 1;
    ull th = g_thresh;
    // scatter into sS + load x_old into sX (per-warp rows only)
#pragma unroll
    for (int nd = 0; nd < 2; ++nd) {
        int n = nbase + nd;
        sX[row0 + nd][l] = reinterpret_cast<const float4*>(xo)[(size_t)n * 32 + l];
        int beg = g_dstPtr[n], end = g_dstPtr[n + 1];
        float4 acc = make_float4(0.f, 0.f, 0.f, 0.f);
        int k = beg;
        for (; k + 1 < end; k += 2) {
            uint2 p0 = g_dstPk[k], p1 = g_dstPk[k + 1];
            float a0 = g_aN[p0.x], a1 = g_aN[p1.x];
            ull key0 = ((ull)__float_as_uint(a0) << 32) | (unsigned)(0xFFFFFFFFu - p0.x);
            ull key1 = ((ull)__float_as_uint(a1) << 32) | (unsigned)(0xFFFFFFFFu - p1.x);
            if (key0 >= th) {
                float4 xv = __ldg(&reinterpret_cast<const float4*>(xo)[(size_t)(p0.y & 0xFFFFu) * 32 + l]);
                float4 rv = reinterpret_cast<const float4*>(g_rel)[(p0.y >> 16) * 32 + l];
                acc.x += a0 * (xv.x + rv.x); acc.y += a0 * (xv.y + rv.y);
                acc.z += a0 * (xv.z + rv.z); acc.w += a0 * (xv.w + rv.w);
            }
            if (key1 >= th) {
                float4 xv = __ldg(&reinterpret_cast<const float4*>(xo)[(size_t)(p1.y & 0xFFFFu) * 32 + l]);
                float4 rv = reinterpret_cast<const float4*>(g_rel)[(p1.y >> 16) * 32 + l];
                acc.x += a1 * (xv.x + rv.x); acc.y += a1 * (xv.y + rv.y);
                acc.z += a1 * (xv.z + rv.z); acc.w += a1 * (xv.w + rv.w);
            }
        }
        if (k < end) {
            uint2 p0 = g_dstPk[k];
            float a0 = g_aN[p0.x];
            ull key0 = ((ull)__float_as_uint(a0) << 32) | (unsigned)(0xFFFFFFFFu - p0.x);
            if (key0 >= th) {
                float4 xv = __ldg(&reinterpret_cast<const float4*>(xo)[(size_t)(p0.y & 0xFFFFu) * 32 + l]);
                float4 rv = reinterpret_cast<const float4*>(g_rel)[(p0.y >> 16) * 32 + l];
                acc.x += a0 * (xv.x + rv.x); acc.y += a0 * (xv.y + rv.y);
                acc.z += a0 * (xv.z + rv.z); acc.w += a0 * (xv.w + rv.w);
            }
        }
        sS[row0 + nd][l] = acc;
    }
    __syncthreads();   // covers weight loads + per-warp tiles

    float acc[2][2][2] = {};
    for (int jv = 0; jv < 16; ++jv) {
        float4 X0a = sX[row0][jv], X1a = sX[row0][16 + jv];
        float4 S0a = sS[row0][jv], S1a = sS[row0][16 + jv];
        float4 X0b = sX[row1][jv], X1b = sX[row1][16 + jv];
        float4 S0b = sS[row1][jv], S1b = sS[row1][16 + jv];
        const float* x0a = (const float*)&X0a; const float* x1a = (const float*)&X1a;
        const float* s0a = (const float*)&S0a; const float* s1a = (const float*)&S1a;
        const float* x0b = (const float*)&X0b; const float* x1b = (const float*)&X1b;
        const float* s0b = (const float*)&S0b; const float* s1b = (const float*)&S1b;
#pragma unroll
        for (int u = 0; u < 4; ++u) {
            int j = jv * 4 + u;
            float wA0 = sWs[j * FD + l], wA1 = sWs[j * FD + 32 + l];
            float wB0 = sW2[j * FD + l], wB1 = sW2[j * FD + 32 + l];
            acc[0][0][0] += x0a[u] * wA0 + s0a[u] * wB0;
            acc[0][0][1] += x0a[u] * wA1 + s0a[u] * wB1;
            acc[0][1][0] += x1a[u] * wA0 + s1a[u] * wB0;
            acc[0][1][1] += x1a[u] * wA1 + s1a[u] * wB1;
            acc[1][0][0] += x0b[u] * wA0 + s0b[u] * wB0;
            acc[1][0][1] += x0b[u] * wA1 + s0b[u] * wB1;
            acc[1][1][0] += x1b[u] * wA0 + s1b[u] * wB0;
            acc[1][1][1] += x1b[u] * wA1 + s1b[u] * wB1;
        }
    }

    const float* sXf = (const float*)sX;
#pragma unroll
    for (int nd = 0; nd < 2; ++nd) {
        int n = nbase + nd;
        int row = row0 + nd;
        float nxacc = 0.f;
#pragma unroll
        for (int b = 0; b < 2; ++b) {
            float v0 = acc[nd][b][0] + sLb[l] + sTr[b * 64 + l];
            float v1 = acc[nd][b][1] + sLb[32 + l] + sTr[b * 64 + 32 + l];
            float s = v0 + v1;
            float q = v0 * v0 + v1 * v1;
#pragma unroll
            for (int o = 16; o; o >>= 1) {
                s += __shfl_xor_sync(0xffffffffu, s, o);
                q += __shfl_xor_sync(0xffffffffu, q, o);
            }
            float mu = s * (1.f / 64.f);
            float var = q * (1.f / 64.f) - mu * mu;
            float rs = rsqrtf(var + 1e-5f);
            v0 = (v0 - mu) * rs * sG[l] + sB[l];
            v1 = (v1 - mu) * rs * sG[32 + l] + sB[32 + l];
            v0 = v0 > 0.f ? v0 : expm1f(v0);
            v1 = v1 > 0.f ? v1 : expm1f(v1);
            float xn0 = v0 + sXf[row * BFDIM + b * 64 + l];
            float xn1 = v1 + sXf[row * BFDIM + b * 64 + 32 + l];
            xn[(size_t)n * BFDIM + b * 64 + l] = xn0;
            xn[(size_t)n * BFDIM + b * 64 + 32 + l] = xn1;
            if (it < 3) {
                nxacc += xn0 * sWa[b * 64 + l] + xn1 * sWa[b * 64 + 32 + l];
                atomicAdd(&racc[b * 64 + l], xn0);
                atomicAdd(&racc[b * 64 + 32 + l], xn1);
            }
        }
        if (it < 3) {
#pragma unroll
            for (int o = 16; o; o >>= 1) nxacc += __shfl_xor_sync(0xffffffffu, nxacc, o);
            if (l == 0) g_nx[n] = nxacc;
        }
    }
    __syncthreads();
    if (it < 3 && tid < BFDIM) atomicAdd(&g_rsum[tid], racc[tid]);
}

// ---------------- launch ----------------
extern "C" void kernel_launch(void* const* d_in, const int* in_sizes, int n_in,
                              void* d_out, int out_size) {
    const int* ei  = (const int*)d_in[0];
    const int* ri  = (const int*)d_in[1];
    const float* bnd = (const float*)d_in[2];
    const float* qi  = (const float*)d_in[3];
    const float* rw  = (const float*)d_in[4];
    const float* rb  = (const float*)d_in[5];
    const float* lw  = (const float*)d_in[6];
    const float* lb  = (const float*)d_in[7];
    const float* trw = (const float*)d_in[8];
    const float* trb = (const float*)d_in[9];
    const float* Wm  = (const float*)d_in[10];
    const float* av  = (const float*)d_in[11];
    const float* lng = (const float*)d_in[12];
    const float* lnb = (const float*)d_in[13];
    float* x0 = (float*)d_out;

    static int attr_done = 0;
    static void* srcCntPtr = nullptr;
    static void* dstCntPtr = nullptr;
    static void* xbufPtr = nullptr;
    if (!attr_done) {
        cudaFuncSetAttribute(k_soft, cudaFuncAttributeMaxDynamicSharedMemorySize, 131072);
        cudaGetSymbolAddress(&srcCntPtr, g_srcCnt);
        cudaGetSymbolAddress(&dstCntPtr, g_dstCnt);
        cudaGetSymbolAddress(&xbufPtr, g_xbuf);
        attr_done = 1;
    }
    float* x1 = (float*)xbufPtr;

    cudaMemsetAsync(srcCntPtr, 0, NN * sizeof(unsigned), 0);
    cudaMemsetAsync(dstCntPtr, 0, NN * sizeof(unsigned), 0);
    k_prep1<<<34 + 1250, 256>>>(qi, rw, rb, Wm, av, lw, ei);
    k_csr_scan<<<1, 1024>>>();
    k_fill_init<<<1250 + 2500, 256>>>(ei, ri, bnd, x0);

    for (int it = 0; it < NITER; ++it) {
        float* xo = (it & 1) ? x1 : x0;
        float* xn = (it & 1) ? x0 : x1;   // it=3 writes x0 = d_out
        k_soft<<<SB, STH, 131072>>>(it, trw, trb);
        k_scat_epi<<<625, 512>>>(xo, xn, lb, lng, lnb, it);
    }
}

// round 10
// speedup vs baseline: 1.0882x; 1.0882x over previous
#include <cuda_runtime.h>
#include <cstdint>
#include <math_constants.h>

#define NN 20000
#define NE 320000
#define BFDIM 128
#define FD 64
#define RD 32
#define KSEL 160000
#define NITER 4
#define SB 148
#define STH 1024

typedef unsigned long long ull;

// ---------------- scratch ----------------
__device__ __align__(16) float g_rel[RD * BFDIM];
__device__ __align__(16) float g_wa[4 * BFDIM];
__device__ float g_drel[4 * RD];
__device__ float g_wsumT[FD * FD];
__device__ float g_w2T[FD * FD];
__device__ float g_tr[BFDIM];
__device__ float g_rsum[BFDIM];
__device__ float g_nx[NN];
__device__ __align__(16) float g_aN[NE];
__device__ __align__(16) float g_scat[NN * BFDIM];
__device__ __align__(16) unsigned g_hist[65536];
__device__ __align__(16) unsigned g_coarse[256];
__device__ unsigned g_cnt1;
__device__ unsigned g_cnt2;
__device__ unsigned g_flagA;
__device__ unsigned g_d0;
__device__ long long g_rem0;
__device__ unsigned g_eqCount;
__device__ int g_eqE[32768];
__device__ unsigned g_eqB[32768];
__device__ ull g_thresh;
// CSR
__device__ int g_srcPtr[NN + 1];
__device__ int g_dstPtr[NN + 1];
__device__ unsigned g_srcCnt[NN];
__device__ unsigned g_dstCnt[NN];
__device__ unsigned g_srcPk[NE];           // e | (r<<19), ordered by src
__device__ __align__(8) uint2 g_dstPk[NE]; // {e, s|(r<<16)}, ordered by dst

// ---------------- prep1: weights + csr count (merged grid) ----------------
__global__ __launch_bounds__(256) void k_prep1(const float* __restrict__ q,
                                               const float* __restrict__ rw,
                                               const float* __restrict__ rb,
                                               const float* __restrict__ Wm,
                                               const float* __restrict__ av,
                                               const float* __restrict__ lw,
                                               const int* __restrict__ ei) {
    if (blockIdx.x < 34) {
        int t = blockIdx.x * blockDim.x + threadIdx.x;
        if (t < 4096) {
            int b = t >> 11, j = t & 2047;
            const float* qr = q + b * FD;
            const float* wr = rw + j * FD;
            float s = rb[j];
#pragma unroll 16
            for (int k = 0; k < FD; k++) s += qr[k] * wr[k];
            g_rel[b * (RD * FD) + j] = s;
        } else if (t < 4608) {
            int u = t - 4096;
            int i = u >> 7, j = u & 127;
            float s = 0.f;
#pragma unroll 16
            for (int f = 0; f < FD; f++) s += Wm[j * FD + f] * av[i * FD + f];
            g_wa[u] = s;
        } else if (t < 8704) {
            int u = t - 4608;
            int j = u >> 6, f = u & 63;
            float w2 = lw[f * 2 * FD + FD + j];
            g_w2T[j * FD + f] = w2;
            g_wsumT[j * FD + f] = lw[f * 2 * FD + j] + w2;
        }
    } else {
        int e = (blockIdx.x - 34) * blockDim.x + threadIdx.x;
        if (e < NE) {
            atomicAdd(&g_srcCnt[ei[e]], 1u);
            atomicAdd(&g_dstCnt[ei[NE + e]], 1u);
        }
    }
}

__global__ __launch_bounds__(1024) void k_csr_scan() {
    __shared__ unsigned ss[1024];
    int t = threadIdx.x;
    if (t < 4 * RD) {
        int i = t >> 5, r = t & 31;
        float s = 0.f;
#pragma unroll 16
        for (int j = 0; j < BFDIM; j++) s += g_rel[r * BFDIM + j] * g_wa[i * BFDIM + j];
        g_drel[t] = s;
    }
    for (int phase = 0; phase < 2; ++phase) {
        unsigned* cnt = phase ? g_dstCnt : g_srcCnt;
        int* ptr = phase ? g_dstPtr : g_srcPtr;
        unsigned loc[20]; unsigned s = 0;
#pragma unroll
        for (int i = 0; i < 20; i++) {
            int idx = t * 20 + i;
            unsigned v = (idx < NN) ? cnt[idx] : 0u;
            loc[i] = s; s += v;
        }
        ss[t] = s;
        __syncthreads();
        for (int off = 1; off < 1024; off <<= 1) {
            unsigned v = (t >= off) ? ss[t - off] : 0u;
            __syncthreads();
            ss[t] += v;
            __syncthreads();
        }
        unsigned base = (t > 0) ? ss[t - 1] : 0u;
#pragma unroll
        for (int i = 0; i < 20; i++) {
            int idx = t * 20 + i;
            if (idx < NN) { ptr[idx] = (int)(base + loc[i]); cnt[idx] = 0u; }
        }
        if (t == 0) ptr[NN] = NE;
        __syncthreads();
    }
}

// ---------------- csr fill + init (merged grid) ----------------
__global__ __launch_bounds__(256) void k_fill_init(const int* __restrict__ ei,
                                                   const int* __restrict__ ri,
                                                   const float* __restrict__ bnd,
                                                   float* __restrict__ x) {
    int tid = threadIdx.x;
    if (blockIdx.x < 1250) {
        int e = blockIdx.x * 256 + tid;
        if (e >= NE) return;
        int s = ei[e];
        unsigned r = (unsigned)ri[e];
        unsigned p = atomicAdd(&g_srcCnt[s], 1u);
        g_srcPk[g_srcPtr[s] + (int)p] = (unsigned)e | (r << 19);
        int d = ei[NE + e];
        unsigned p2 = atomicAdd(&g_dstCnt[d], 1u);
        g_dstPk[g_dstPtr[d] + (int)p2] = make_uint2((unsigned)e, (unsigned)s | (r << 16));
    } else {
        __shared__ float racc[BFDIM];
        if (tid < BFDIM) racc[tid] = 0.f;
        __syncthreads();
        int warp = ((blockIdx.x - 1250) * 256 + tid) >> 5;
        int l = tid & 31;
        if (warp < NN) {
            float4 v = reinterpret_cast<const float4*>(bnd)[(size_t)warp * 32 + l];
            reinterpret_cast<float4*>(x)[(size_t)warp * 32 + l] = v;
            float4 w = reinterpret_cast<const float4*>(g_wa)[l];
            float s = v.x * w.x + v.y * w.y + v.z * w.z + v.w * w.w;
#pragma unroll
            for (int o = 16; o; o >>= 1) s += __shfl_xor_sync(0xffffffffu, s, o);
            if (l == 0) g_nx[warp] = s;
            atomicAdd(&racc[l * 4 + 0], v.x);
            atomicAdd(&racc[l * 4 + 1], v.y);
            atomicAdd(&racc[l * 4 + 2], v.z);
            atomicAdd(&racc[l * 4 + 3], v.w);
        }
        __syncthreads();
        if (tid < BFDIM) atomicAdd(&g_rsum[tid], racc[tid]);
    }
}

// ---------------- descending 256-bin pick helper ----------------
__device__ __forceinline__ void pick_desc(unsigned* h, unsigned* sc, int t, long long R,
                                          unsigned* outDigit, long long* outRem) {
    if (t < 256) sc[t] = h[255 - t];
    __syncthreads();
    for (int off = 1; off < 256; off <<= 1) {
        unsigned v = (t < 256 && t >= off) ? sc[t - off] : 0u;
        __syncthreads();
        if (t < 256) sc[t] += v;
        __syncthreads();
    }
    if (t < 256) {
        long long incl = (long long)sc[t];
        long long before = incl - (long long)h[255 - t];
        if (before < R && R <= incl) { *outDigit = (unsigned)(255 - t); *outRem = R - before; }
    }
    __syncthreads();
}

// ==== persistent fused: softmax + hist + pick + collect + resolve + tr ====
__global__ __launch_bounds__(STH) void k_soft(int it, const float* __restrict__ trw,
                                              const float* __restrict__ trb) {
    extern __shared__ unsigned sh[];   // 32768 words packed hist
    __shared__ unsigned hh[256], hsc[256];
    __shared__ float sdrel[RD];
    __shared__ unsigned selDigit; __shared__ long long selRem;
    __shared__ unsigned isLast1, isLast2, candCnt;
    __shared__ int cand[4096];
    int tid = threadIdx.x;
    for (int i = tid; i < 32768; i += STH) sh[i] = 0u;
    if (tid < RD) sdrel[tid] = g_drel[it * RD + tid];
    __syncthreads();
    int l16 = tid & 15;
    unsigned hmask = ((tid & 16) ? 0xFFFF0000u : 0x0000FFFFu);
    int grp = blockIdx.x * (STH / 16) + (tid >> 4);
    int totalGrp = SB * (STH / 16);
    for (int n = grp; n < NN; n += totalGrp) {
        int beg = g_srcPtr[n], end = g_srcPtr[n + 1];
        if (beg == end) continue;
        float nx = g_nx[n];
        float tc[4]; unsigned pkc[4];
        float m = -CUDART_INF_F;
        int k0 = beg + l16;
#pragma unroll
        for (int u = 0; u < 4; ++u) {
            int kk = k0 + u * 16;
            float t = -CUDART_INF_F; unsigned pk = 0u;
            if (kk < end) {
                pk = g_srcPk[kk];
                t = nx + sdrel[pk >> 19];
                t = t > 0.f ? t : 0.2f * t;
            }
            tc[u] = t; pkc[u] = pk;
            m = fmaxf(m, t);
        }
        for (int kk = k0 + 64; kk < end; kk += 16) {
            unsigned pk = g_srcPk[kk];
            float t = nx + sdrel[pk >> 19];
            t = t > 0.f ? t : 0.2f * t;
            m = fmaxf(m, t);
        }
#pragma unroll
        for (int o = 8; o; o >>= 1) m = fmaxf(m, __shfl_xor_sync(hmask, m, o));
        float sum = 0.f;
#pragma unroll
        for (int u = 0; u < 4; ++u) {
            if (k0 + u * 16 < end) {
                float ex = expf(tc[u] - m);
                tc[u] = ex;
                sum += ex;
            }
        }
        for (int kk = k0 + 64; kk < end; kk += 16) {
            unsigned pk = g_srcPk[kk];
            float t = nx + sdrel[pk >> 19];
            t = t > 0.f ? t : 0.2f * t;
            sum += expf(t - m);
        }
#pragma unroll
        for (int o = 8; o; o >>= 1) sum += __shfl_xor_sync(hmask, sum, o);
        float invd = 1.f / (sum + 1e-16f);
#pragma unroll
        for (int u = 0; u < 4; ++u) {
            if (k0 + u * 16 < end) {
                float a = tc[u] * invd;
                g_aN[pkc[u] & 0x7FFFFu] = a;
                unsigned d = __float_as_uint(a) >> 16;
                atomicAdd(&sh[d >> 1], (d & 1) ? 65536u : 1u);
            }
        }
        for (int kk = k0 + 64; kk < end; kk += 16) {
            unsigned pk = g_srcPk[kk];
            float t = nx + sdrel[pk >> 19];
            t = t > 0.f ? t : 0.2f * t;
            float a = expf(t - m) * invd;
            g_aN[pk & 0x7FFFFu] = a;
            unsigned d = __float_as_uint(a) >> 16;
            atomicAdd(&sh[d >> 1], (d & 1) ? 65536u : 1u);
        }
    }
    __syncthreads();
    // merge packed smem hist -> global fine + coarse
    {
        int w = tid >> 5, l = tid & 31;
        for (int g = w; g < 256; g += (STH / 32)) {
            unsigned gsum = 0;
            int base = g * 128;
#pragma unroll
            for (int j = 0; j < 4; ++j) {
                int wi = base + j * 32 + l;
                unsigned word = sh[wi];
                if (word) {
                    unsigned lo = word & 0xFFFFu, hi = word >> 16;
                    if (lo) atomicAdd(&g_hist[2 * wi], lo);
                    if (hi) atomicAdd(&g_hist[2 * wi + 1], hi);
                    gsum += lo + hi;
                }
            }
#pragma unroll
            for (int o = 16; o; o >>= 1) gsum += __shfl_xor_sync(0xffffffffu, gsum, o);
            if (l == 0 && gsum) atomicAdd(&g_coarse[g], gsum);
        }
    }
    __threadfence();
    if (tid == 0) isLast1 = (atomicAdd(&g_cnt1, 1u) == gridDim.x - 1u) ? 1u : 0u;
    __syncthreads();
    if (isLast1) {
        if (tid < 256) hh[tid] = g_coarse[tid];
        __syncthreads();
        pick_desc(hh, hsc, tid, (long long)KSEL, &selDigit, &selRem);
        unsigned grpd = selDigit; long long R1 = selRem;
        if (tid < 256) hh[tid] = g_hist[grpd * 256 + tid];
        __syncthreads();
        pick_desc(hh, hsc, tid, R1, &selDigit, &selRem);
        if (tid == 0) {
            g_d0 = (grpd << 8) | selDigit;
            g_rem0 = selRem;
            g_eqCount = 0u;
        }
        __syncthreads();
        uint4 z = make_uint4(0u, 0u, 0u, 0u);
        uint4* H = reinterpret_cast<uint4*>(g_hist);
        for (int i = tid; i < 16384; i += STH) H[i] = z;
        if (tid < 64) reinterpret_cast<uint4*>(g_coarse)[tid] = z;
        __threadfence();
        __syncthreads();
        if (tid == 0) atomicExch(&g_flagA, 1u);
    } else {
        if (tid == 0) { while (atomicAdd(&g_flagA, 0u) == 0u) { __nanosleep(64); } }
        __syncthreads();
        __threadfence();
    }
    // ---- all blocks: parallel collect of bucket d0 ----
    {
        unsigned d0 = g_d0;
        const float4* aN4 = reinterpret_cast<const float4*>(g_aN);
        int stride = gridDim.x * STH;
        for (int i = blockIdx.x * STH + tid; i < NE / 4; i += stride) {
            float4 v = aN4[i];
            const float* vf = (const float*)&v;
#pragma unroll
            for (int c = 0; c < 4; ++c) {
                unsigned bits = __float_as_uint(vf[c]);
                if ((bits >> 16) == d0) {
                    unsigned p = atomicAdd(&g_eqCount, 1u);
                    if (p < 32768u) { g_eqE[p] = 4 * i + c; g_eqB[p] = bits; }
                }
            }
        }
    }
    __threadfence();
    if (tid == 0) isLast2 = (atomicAdd(&g_cnt2, 1u) == gridDim.x - 1u) ? 1u : 0u;
    __syncthreads();
    if (!isLast2) return;
    // ---- last block: resolve + tr vector ----
    {
        int c = (int)min(g_eqCount, 32768u);
        long long r0 = g_rem0;
        unsigned d0 = g_d0;
        if (tid < 256) hh[tid] = 0u;
        __syncthreads();
        for (int i = tid; i < c; i += STH) atomicAdd(&hh[(g_eqB[i] >> 8) & 0xFFu], 1u);
        __syncthreads();
        pick_desc(hh, hsc, tid, r0, &selDigit, &selRem);
        unsigned b1 = selDigit; long long r1 = selRem;
        if (tid < 256) hh[tid] = 0u;
        __syncthreads();
        for (int i = tid; i < c; i += STH) {
            unsigned bits = g_eqB[i];
            if (((bits >> 8) & 0xFFu) == b1) atomicAdd(&hh[bits & 0xFFu], 1u);
        }
        __syncthreads();
        pick_desc(hh, hsc, tid, r1, &selDigit, &selRem);
        unsigned T = (d0 << 16) | (b1 << 8) | selDigit;
        int r2 = (int)selRem;
        if (tid == 0) candCnt = 0u;
        __syncthreads();
        for (int i = tid; i < c; i += STH) {
            if (g_eqB[i] == T) {
                unsigned p = atomicAdd(&candCnt, 1u);
                if (p < 4096u) cand[p] = g_eqE[i];
            }
        }
        __syncthreads();
        int tc2 = (int)min(candCnt, 4096u);
        for (int i = tid; i < tc2; i += STH) {
            int e = cand[i];
            int cnt = 0;
            for (int j = 0; j < tc2; ++j) cnt += (cand[j] < e) ? 1 : 0;
            if (cnt == r2 - 1)
                g_thresh = ((ull)T << 32) | (unsigned)(0xFFFFFFFFu - (unsigned)e);
        }
        // trans-readout vector (rsum is complete from previous epi/init)
        float trv = 0.f;
        if (tid < BFDIM) {
            int b = tid >> 6, f = tid & 63;
            const float* r = g_rsum + b * FD;
            float s = trb[f];
            const float inv = 1.f / (float)NN;
#pragma unroll 16
            for (int j = 0; j < FD; j++) s += (r[j] * inv) * trw[f * FD + j];
            trv = s;
        }
        __syncthreads();
        if (tid < BFDIM) { g_tr[tid] = trv; g_rsum[tid] = 0.f; }
        __syncthreads();
        if (tid == 0) { g_cnt1 = 0u; g_cnt2 = 0u; g_flagA = 0u; }
    }
}

// -------- scatter by dst (warp per node, high occupancy) ----------
__global__ __launch_bounds__(256) void k_scatter(const float* __restrict__ x) {
    int tid = threadIdx.x;
    int warp = (blockIdx.x * 256 + tid) >> 5;
    int l = tid & 31;
    if (warp >= NN) return;
    int beg = g_dstPtr[warp], end = g_dstPtr[warp + 1];
    ull th = g_thresh;
    float4 acc = make_float4(0.f, 0.f, 0.f, 0.f);
    int k = beg;
    for (; k + 1 < end; k += 2) {
        uint2 p0 = g_dstPk[k], p1 = g_dstPk[k + 1];
        float a0 = g_aN[p0.x], a1 = g_aN[p1.x];
        ull key0 = ((ull)__float_as_uint(a0) << 32) | (unsigned)(0xFFFFFFFFu - p0.x);
        ull key1 = ((ull)__float_as_uint(a1) << 32) | (unsigned)(0xFFFFFFFFu - p1.x);
        if (key0 >= th) {
            float4 xv = __ldg(&reinterpret_cast<const float4*>(x)[(size_t)(p0.y & 0xFFFFu) * 32 + l]);
            float4 rv = reinterpret_cast<const float4*>(g_rel)[(p0.y >> 16) * 32 + l];
            acc.x += a0 * (xv.x + rv.x); acc.y += a0 * (xv.y + rv.y);
            acc.z += a0 * (xv.z + rv.z); acc.w += a0 * (xv.w + rv.w);
        }
        if (key1 >= th) {
            float4 xv = __ldg(&reinterpret_cast<const float4*>(x)[(size_t)(p1.y & 0xFFFFu) * 32 + l]);
            float4 rv = reinterpret_cast<const float4*>(g_rel)[(p1.y >> 16) * 32 + l];
            acc.x += a1 * (xv.x + rv.x); acc.y += a1 * (xv.y + rv.y);
            acc.z += a1 * (xv.z + rv.z); acc.w += a1 * (xv.w + rv.w);
        }
    }
    if (k < end) {
        uint2 p0 = g_dstPk[k];
        float a0 = g_aN[p0.x];
        ull key0 = ((ull)__float_as_uint(a0) << 32) | (unsigned)(0xFFFFFFFFu - p0.x);
        if (key0 >= th) {
            float4 xv = __ldg(&reinterpret_cast<const float4*>(x)[(size_t)(p0.y & 0xFFFFu) * 32 + l]);
            float4 rv = reinterpret_cast<const float4*>(g_rel)[(p0.y >> 16) * 32 + l];
            acc.x += a0 * (xv.x + rv.x); acc.y += a0 * (xv.y + rv.y);
            acc.z += a0 * (xv.z + rv.z); acc.w += a0 * (xv.w + rv.w);
        }
    }
    reinterpret_cast<float4*>(g_scat)[(size_t)warp * 32 + l] = acc;
}

// ------ fused layer linear + broadcast + LN + ELU + residual + next nx/rsum ----
__global__ __launch_bounds__(512) void k_epi(float* __restrict__ x,
                                             const float* __restrict__ lb,
                                             const float* __restrict__ lng,
                                             const float* __restrict__ lnb,
                                             int it) {
    __shared__ float sWs[FD * FD];
    __shared__ float sW2[FD * FD];
    __shared__ float sTr[BFDIM];
    __shared__ float sWa[BFDIM];
    __shared__ float racc[BFDIM];
    __shared__ float sLb[FD], sG[FD], sB[FD];
    __shared__ float4 sX[32][32];
    __shared__ float4 sS[32][32];
    int tid = threadIdx.x;
    for (int i = tid; i < FD * FD; i += 512) { sWs[i] = g_wsumT[i]; sW2[i] = g_w2T[i]; }
    if (tid < BFDIM) {
        sTr[tid] = g_tr[tid];
        sWa[tid] = (it < 3) ? g_wa[(it + 1) * BFDIM + tid] : 0.f;
        racc[tid] = 0.f;
    }
    if (tid < FD) { sLb[tid] = lb[tid]; sG[tid] = lng[tid]; sB[tid] = lnb[tid]; }
    __syncthreads();
    int w = tid >> 5, l = tid & 31;
    int nbase = blockIdx.x * 32 + w * 2;
    int row0 = w * 2, row1 = w * 2 + 1;
#pragma unroll
    for (int nd = 0; nd < 2; ++nd) {
        int n = nbase + nd;
        sX[row0 + nd][l] = reinterpret_cast<const float4*>(x)[(size_t)n * 32 + l];
        sS[row0 + nd][l] = reinterpret_cast<const float4*>(g_scat)[(size_t)n * 32 + l];
    }
    __syncwarp();

    float acc[2][2][2] = {};
    for (int jv = 0; jv < 16; ++jv) {
        float4 X0a = sX[row0][jv], X1a = sX[row0][16 + jv];
        float4 S0a = sS[row0][jv], S1a = sS[row0][16 + jv];
        float4 X0b = sX[row1][jv], X1b = sX[row1][16 + jv];
        float4 S0b = sS[row1][jv], S1b = sS[row1][16 + jv];
        const float* x0a = (const float*)&X0a; const float* x1a = (const float*)&X1a;
        const float* s0a = (const float*)&S0a; const float* s1a = (const float*)&S1a;
        const float* x0b = (const float*)&X0b; const float* x1b = (const float*)&X1b;
        const float* s0b = (const float*)&S0b; const float* s1b = (const float*)&S1b;
#pragma unroll
        for (int u = 0; u < 4; ++u) {
            int j = jv * 4 + u;
            float wA0 = sWs[j * FD + l], wA1 = sWs[j * FD + 32 + l];
            float wB0 = sW2[j * FD + l], wB1 = sW2[j * FD + 32 + l];
            acc[0][0][0] += x0a[u] * wA0 + s0a[u] * wB0;
            acc[0][0][1] += x0a[u] * wA1 + s0a[u] * wB1;
            acc[0][1][0] += x1a[u] * wA0 + s1a[u] * wB0;
            acc[0][1][1] += x1a[u] * wA1 + s1a[u] * wB1;
            acc[1][0][0] += x0b[u] * wA0 + s0b[u] * wB0;
            acc[1][0][1] += x0b[u] * wA1 + s0b[u] * wB1;
            acc[1][1][0] += x1b[u] * wA0 + s1b[u] * wB0;
            acc[1][1][1] += x1b[u] * wA1 + s1b[u] * wB1;
        }
    }

    const float* sXf = (const float*)sX;
#pragma unroll
    for (int nd = 0; nd < 2; ++nd) {
        int n = nbase + nd;
        int row = row0 + nd;
        float nxacc = 0.f;
#pragma unroll
        for (int b = 0; b < 2; ++b) {
            float v0 = acc[nd][b][0] + sLb[l] + sTr[b * 64 + l];
            float v1 = acc[nd][b][1] + sLb[32 + l] + sTr[b * 64 + 32 + l];
            float s = v0 + v1;
            float q = v0 * v0 + v1 * v1;
#pragma unroll
            for (int o = 16; o; o >>= 1) {
                s += __shfl_xor_sync(0xffffffffu, s, o);
                q += __shfl_xor_sync(0xffffffffu, q, o);
            }
            float mu = s * (1.f / 64.f);
            float var = q * (1.f / 64.f) - mu * mu;
            float rs = rsqrtf(var + 1e-5f);
            v0 = (v0 - mu) * rs * sG[l] + sB[l];
            v1 = (v1 - mu) * rs * sG[32 + l] + sB[32 + l];
            v0 = v0 > 0.f ? v0 : expm1f(v0);
            v1 = v1 > 0.f ? v1 : expm1f(v1);
            float xn0 = v0 + sXf[row * BFDIM + b * 64 + l];
            float xn1 = v1 + sXf[row * BFDIM + b * 64 + 32 + l];
            x[(size_t)n * BFDIM + b * 64 + l] = xn0;
            x[(size_t)n * BFDIM + b * 64 + 32 + l] = xn1;
            if (it < 3) {
                nxacc += xn0 * sWa[b * 64 + l] + xn1 * sWa[b * 64 + 32 + l];
                atomicAdd(&racc[b * 64 + l], xn0);
                atomicAdd(&racc[b * 64 + 32 + l], xn1);
            }
        }
        if (it < 3) {
#pragma unroll
            for (int o = 16; o; o >>= 1) nxacc += __shfl_xor_sync(0xffffffffu, nxacc, o);
            if (l == 0) g_nx[n] = nxacc;
        }
    }
    __syncthreads();
    if (it < 3 && tid < BFDIM) atomicAdd(&g_rsum[tid], racc[tid]);
}

// ---------------- launch ----------------
extern "C" void kernel_launch(void* const* d_in, const int* in_sizes, int n_in,
                              void* d_out, int out_size) {
    const int* ei  = (const int*)d_in[0];
    const int* ri  = (const int*)d_in[1];
    const float* bnd = (const float*)d_in[2];
    const float* qi  = (const float*)d_in[3];
    const float* rw  = (const float*)d_in[4];
    const float* rb  = (const float*)d_in[5];
    const float* lw  = (const float*)d_in[6];
    const float* lb  = (const float*)d_in[7];
    const float* trw = (const float*)d_in[8];
    const float* trb = (const float*)d_in[9];
    const float* Wm  = (const float*)d_in[10];
    const float* av  = (const float*)d_in[11];
    const float* lng = (const float*)d_in[12];
    const float* lnb = (const float*)d_in[13];
    float* x = (float*)d_out;

    static int attr_done = 0;
    static void* srcCntPtr = nullptr;
    static void* dstCntPtr = nullptr;
    if (!attr_done) {
        cudaFuncSetAttribute(k_soft, cudaFuncAttributeMaxDynamicSharedMemorySize, 131072);
        cudaGetSymbolAddress(&srcCntPtr, g_srcCnt);
        cudaGetSymbolAddress(&dstCntPtr, g_dstCnt);
        attr_done = 1;
    }

    cudaMemsetAsync(srcCntPtr, 0, NN * sizeof(unsigned), 0);
    cudaMemsetAsync(dstCntPtr, 0, NN * sizeof(unsigned), 0);
    k_prep1<<<34 + 1250, 256>>>(qi, rw, rb, Wm, av, lw, ei);
    k_csr_scan<<<1, 1024>>>();
    k_fill_init<<<1250 + 2500, 256>>>(ei, ri, bnd, x);

    for (int it = 0; it < NITER; ++it) {
        k_soft<<<SB, STH, 131072>>>(it, trw, trb);
        k_scatter<<<2500, 256>>>(x);
        k_epi<<<625, 512>>>(x, lb, lng, lnb, it);
    }
}

// round 11
// speedup vs baseline: 1.0963x; 1.0074x over previous
#include <cuda_runtime.h>
#include <cstdint>
#include <math_constants.h>

#define NN 20000
#define NE 320000
#define BFDIM 128
#define FD 64
#define RD 32
#define KSEL 160000
#define NITER 4
#define SB 148
#define STH 1024

typedef unsigned long long ull;

// ---------------- scratch ----------------
__device__ __align__(16) float g_rel[RD * BFDIM];
__device__ __align__(16) float g_wa[4 * BFDIM];
__device__ float g_drel[4 * RD];
__device__ float g_wsumT[FD * FD];
__device__ float g_w2T[FD * FD];
__device__ float g_tr[BFDIM];
__device__ float g_rsum[BFDIM];
__device__ float g_nx[NN];
__device__ __align__(16) float g_alphaNR[NN * RD];   // per (node, relation) alpha
__device__ __align__(16) unsigned g_cntNR[NN * RD];  // per (node, relation) edge count
__device__ __align__(16) float g_scat[NN * BFDIM];
__device__ __align__(16) unsigned g_hist[65536];
__device__ __align__(16) unsigned g_coarse[256];
__device__ unsigned g_cnt1;
__device__ unsigned g_cnt2;
__device__ unsigned g_flagA;
__device__ unsigned g_d0;
__device__ long long g_rem0;
__device__ unsigned g_eqCount;
__device__ int g_eqE[32768];
__device__ unsigned g_eqB[32768];
__device__ ull g_thresh;
// CSR
__device__ int g_srcPtr[NN + 1];
__device__ int g_dstPtr[NN + 1];
__device__ unsigned g_srcCnt[NN];
__device__ unsigned g_dstCnt[NN];
__device__ unsigned g_srcPk[NE];           // e | (r<<19), ordered by src
__device__ __align__(8) uint2 g_dstPk[NE]; // {e, s|(r<<16)}, ordered by dst

// ---------------- prep1: weights + csr count (merged grid) ----------------
__global__ __launch_bounds__(256) void k_prep1(const float* __restrict__ q,
                                               const float* __restrict__ rw,
                                               const float* __restrict__ rb,
                                               const float* __restrict__ Wm,
                                               const float* __restrict__ av,
                                               const float* __restrict__ lw,
                                               const int* __restrict__ ei) {
    if (blockIdx.x < 34) {
        int t = blockIdx.x * blockDim.x + threadIdx.x;
        if (t < 4096) {
            int b = t >> 11, j = t & 2047;
            const float* qr = q + b * FD;
            const float* wr = rw + j * FD;
            float s = rb[j];
#pragma unroll 16
            for (int k = 0; k < FD; k++) s += qr[k] * wr[k];
            g_rel[b * (RD * FD) + j] = s;
        } else if (t < 4608) {
            int u = t - 4096;
            int i = u >> 7, j = u & 127;
            float s = 0.f;
#pragma unroll 16
            for (int f = 0; f < FD; f++) s += Wm[j * FD + f] * av[i * FD + f];
            g_wa[u] = s;
        } else if (t < 8704) {
            int u = t - 4608;
            int j = u >> 6, f = u & 63;
            float w2 = lw[f * 2 * FD + FD + j];
            g_w2T[j * FD + f] = w2;
            g_wsumT[j * FD + f] = lw[f * 2 * FD + j] + w2;
        }
    } else {
        int e = (blockIdx.x - 34) * blockDim.x + threadIdx.x;
        if (e < NE) {
            atomicAdd(&g_srcCnt[ei[e]], 1u);
            atomicAdd(&g_dstCnt[ei[NE + e]], 1u);
        }
    }
}

__global__ __launch_bounds__(1024) void k_csr_scan() {
    __shared__ unsigned ss[1024];
    int t = threadIdx.x;
    if (t < 4 * RD) {
        int i = t >> 5, r = t & 31;
        float s = 0.f;
#pragma unroll 16
        for (int j = 0; j < BFDIM; j++) s += g_rel[r * BFDIM + j] * g_wa[i * BFDIM + j];
        g_drel[t] = s;
    }
    for (int phase = 0; phase < 2; ++phase) {
        unsigned* cnt = phase ? g_dstCnt : g_srcCnt;
        int* ptr = phase ? g_dstPtr : g_srcPtr;
        unsigned loc[20]; unsigned s = 0;
#pragma unroll
        for (int i = 0; i < 20; i++) {
            int idx = t * 20 + i;
            unsigned v = (idx < NN) ? cnt[idx] : 0u;
            loc[i] = s; s += v;
        }
        ss[t] = s;
        __syncthreads();
        for (int off = 1; off < 1024; off <<= 1) {
            unsigned v = (t >= off) ? ss[t - off] : 0u;
            __syncthreads();
            ss[t] += v;
            __syncthreads();
        }
        unsigned base = (t > 0) ? ss[t - 1] : 0u;
#pragma unroll
        for (int i = 0; i < 20; i++) {
            int idx = t * 20 + i;
            if (idx < NN) { ptr[idx] = (int)(base + loc[i]); cnt[idx] = 0u; }
        }
        if (t == 0) ptr[NN] = NE;
        __syncthreads();
    }
}

// ---------------- csr fill (+ per-(n,r) counts) + init (merged grid) ----------------
__global__ __launch_bounds__(256) void k_fill_init(const int* __restrict__ ei,
                                                   const int* __restrict__ ri,
                                                   const float* __restrict__ bnd,
                                                   float* __restrict__ x) {
    int tid = threadIdx.x;
    if (blockIdx.x < 1250) {
        int e = blockIdx.x * 256 + tid;
        if (e >= NE) return;
        int s = ei[e];
        unsigned r = (unsigned)ri[e];
        unsigned p = atomicAdd(&g_srcCnt[s], 1u);
        g_srcPk[g_srcPtr[s] + (int)p] = (unsigned)e | (r << 19);
        atomicAdd(&g_cntNR[s * RD + r], 1u);
        int d = ei[NE + e];
        unsigned p2 = atomicAdd(&g_dstCnt[d], 1u);
        g_dstPk[g_dstPtr[d] + (int)p2] = make_uint2((unsigned)e, (unsigned)s | (r << 16));
    } else {
        __shared__ float racc[BFDIM];
        if (tid < BFDIM) racc[tid] = 0.f;
        __syncthreads();
        int warp = ((blockIdx.x - 1250) * 256 + tid) >> 5;
        int l = tid & 31;
        if (warp < NN) {
            float4 v = reinterpret_cast<const float4*>(bnd)[(size_t)warp * 32 + l];
            reinterpret_cast<float4*>(x)[(size_t)warp * 32 + l] = v;
            float4 w = reinterpret_cast<const float4*>(g_wa)[l];
            float s = v.x * w.x + v.y * w.y + v.z * w.z + v.w * w.w;
#pragma unroll
            for (int o = 16; o; o >>= 1) s += __shfl_xor_sync(0xffffffffu, s, o);
            if (l == 0) g_nx[warp] = s;
            atomicAdd(&racc[l * 4 + 0], v.x);
            atomicAdd(&racc[l * 4 + 1], v.y);
            atomicAdd(&racc[l * 4 + 2], v.z);
            atomicAdd(&racc[l * 4 + 3], v.w);
        }
        __syncthreads();
        if (tid < BFDIM) atomicAdd(&g_rsum[tid], racc[tid]);
    }
}

// ---------------- descending 256-bin pick helper ----------------
__device__ __forceinline__ void pick_desc(unsigned* h, unsigned* sc, int t, long long R,
                                          unsigned* outDigit, long long* outRem) {
    if (t < 256) sc[t] = h[255 - t];
    __syncthreads();
    for (int off = 1; off < 256; off <<= 1) {
        unsigned v = (t < 256 && t >= off) ? sc[t - off] : 0u;
        __syncthreads();
        if (t < 256) sc[t] += v;
        __syncthreads();
    }
    if (t < 256) {
        long long incl = (long long)sc[t];
        long long before = incl - (long long)h[255 - t];
        if (before < R && R <= incl) { *outDigit = (unsigned)(255 - t); *outRem = R - before; }
    }
    __syncthreads();
}

// ==== persistent fused: (n,r)-softmax + hist + pick + collect + resolve + tr ====
__global__ __launch_bounds__(STH) void k_soft(int it, const float* __restrict__ trw,
                                              const float* __restrict__ trb) {
    extern __shared__ unsigned sh[];   // 32768 words packed hist
    __shared__ unsigned hh[256], hsc[256];
    __shared__ unsigned selDigit; __shared__ long long selRem;
    __shared__ unsigned isLast1, isLast2, candCnt;
    __shared__ int cand[4096];
    int tid = threadIdx.x;
    int l = tid & 31;
    for (int i = tid; i < 32768; i += STH) sh[i] = 0u;
    __syncthreads();
    float dr = g_drel[it * RD + l];      // per-thread fixed relation score
    int warp = blockIdx.x * (STH / 32) + (tid >> 5);
    int totalWarps = SB * (STH / 32);
    // ---- phase 1: warp per node, lane = relation ----
    for (int n = warp; n < NN; n += totalWarps) {
        unsigned c = g_cntNR[n * RD + l];
        bool valid = (c != 0u);
        unsigned vm = __ballot_sync(0xffffffffu, valid);
        if (vm == 0u) { reinterpret_cast<float4*>(g_alphaNR)[n * 8 + (l & 7)] = make_float4(0,0,0,0); continue; }
        float nx = g_nx[n];
        float t = nx + dr;
        t = t > 0.f ? t : 0.2f * t;
        float tv = valid ? t : -CUDART_INF_F;
        float m = tv;
#pragma unroll
        for (int o = 16; o; o >>= 1) m = fmaxf(m, __shfl_xor_sync(0xffffffffu, m, o));
        float ex = valid ? expf(t - m) : 0.f;
        float cs = (float)c * ex;
#pragma unroll
        for (int o = 16; o; o >>= 1) cs += __shfl_xor_sync(0xffffffffu, cs, o);
        float a = ex * (1.f / (cs + 1e-16f));
        g_alphaNR[n * RD + l] = a;
        if (valid) {
            unsigned d = __float_as_uint(a) >> 16;
            atomicAdd(&sh[d >> 1], (d & 1) ? (c << 16) : c);
        }
    }
    __syncthreads();
    // merge packed smem hist -> global fine + coarse
    {
        int w = tid >> 5;
        for (int g = w; g < 256; g += (STH / 32)) {
            unsigned gsum = 0;
            int base = g * 128;
#pragma unroll
            for (int j = 0; j < 4; ++j) {
                int wi = base + j * 32 + l;
                unsigned word = sh[wi];
                if (word) {
                    unsigned lo = word & 0xFFFFu, hi = word >> 16;
                    if (lo) atomicAdd(&g_hist[2 * wi], lo);
                    if (hi) atomicAdd(&g_hist[2 * wi + 1], hi);
                    gsum += lo + hi;
                }
            }
#pragma unroll
            for (int o = 16; o; o >>= 1) gsum += __shfl_xor_sync(0xffffffffu, gsum, o);
            if (l == 0 && gsum) atomicAdd(&g_coarse[g], gsum);
        }
    }
    __threadfence();
    if (tid == 0) isLast1 = (atomicAdd(&g_cnt1, 1u) == gridDim.x - 1u) ? 1u : 0u;
    __syncthreads();
    if (isLast1) {
        if (tid < 256) hh[tid] = g_coarse[tid];
        __syncthreads();
        pick_desc(hh, hsc, tid, (long long)KSEL, &selDigit, &selRem);
        unsigned grpd = selDigit; long long R1 = selRem;
        if (tid < 256) hh[tid] = g_hist[grpd * 256 + tid];
        __syncthreads();
        pick_desc(hh, hsc, tid, R1, &selDigit, &selRem);
        if (tid == 0) {
            g_d0 = (grpd << 8) | selDigit;
            g_rem0 = selRem;
            g_eqCount = 0u;
        }
        __syncthreads();
        uint4 z = make_uint4(0u, 0u, 0u, 0u);
        uint4* H = reinterpret_cast<uint4*>(g_hist);
        for (int i = tid; i < 16384; i += STH) H[i] = z;
        if (tid < 64) reinterpret_cast<uint4*>(g_coarse)[tid] = z;
        __threadfence();
        __syncthreads();
        if (tid == 0) atomicExch(&g_flagA, 1u);
    } else {
        if (tid == 0) { while (atomicAdd(&g_flagA, 0u) == 0u) { __nanosleep(64); } }
        __syncthreads();
        __threadfence();
    }
    // ---- collect: warp per node with early-out ballot ----
    {
        unsigned d0 = g_d0;
        for (int n = warp; n < NN; n += totalWarps) {
            float a = g_alphaNR[n * RD + l];
            unsigned bits = __float_as_uint(a);
            unsigned match = __ballot_sync(0xffffffffu, (bits >> 16) == d0 && bits != 0u);
            if (match == 0u) continue;
            int beg = g_srcPtr[n], end = g_srcPtr[n + 1];
            for (int k0 = beg; k0 < end; k0 += 32) {
                int k = k0 + l;
                bool act = (k < end);
                unsigned pk = act ? g_srcPk[k] : 0u;
                unsigned r = pk >> 19;
                unsigned br = __shfl_sync(0xffffffffu, bits, (int)r);
                if (act && ((match >> r) & 1u)) {
                    unsigned p = atomicAdd(&g_eqCount, 1u);
                    if (p < 32768u) { g_eqE[p] = (int)(pk & 0x7FFFFu); g_eqB[p] = br; }
                }
            }
        }
    }
    __threadfence();
    if (tid == 0) isLast2 = (atomicAdd(&g_cnt2, 1u) == gridDim.x - 1u) ? 1u : 0u;
    __syncthreads();
    if (!isLast2) return;
    // ---- last block: resolve + tr vector ----
    {
        int c = (int)min(g_eqCount, 32768u);
        long long r0 = g_rem0;
        unsigned d0 = g_d0;
        if (tid < 256) hh[tid] = 0u;
        __syncthreads();
        for (int i = tid; i < c; i += STH) atomicAdd(&hh[(g_eqB[i] >> 8) & 0xFFu], 1u);
        __syncthreads();
        pick_desc(hh, hsc, tid, r0, &selDigit, &selRem);
        unsigned b1 = selDigit; long long r1 = selRem;
        if (tid < 256) hh[tid] = 0u;
        __syncthreads();
        for (int i = tid; i < c; i += STH) {
            unsigned bits = g_eqB[i];
            if (((bits >> 8) & 0xFFu) == b1) atomicAdd(&hh[bits & 0xFFu], 1u);
        }
        __syncthreads();
        pick_desc(hh, hsc, tid, r1, &selDigit, &selRem);
        unsigned T = (d0 << 16) | (b1 << 8) | selDigit;
        int r2 = (int)selRem;
        if (tid == 0) candCnt = 0u;
        __syncthreads();
        for (int i = tid; i < c; i += STH) {
            if (g_eqB[i] == T) {
                unsigned p = atomicAdd(&candCnt, 1u);
                if (p < 4096u) cand[p] = g_eqE[i];
            }
        }
        __syncthreads();
        int tc2 = (int)min(candCnt, 4096u);
        for (int i = tid; i < tc2; i += STH) {
            int e = cand[i];
            int cnt = 0;
            for (int j = 0; j < tc2; ++j) cnt += (cand[j] < e) ? 1 : 0;
            if (cnt == r2 - 1)
                g_thresh = ((ull)T << 32) | (unsigned)(0xFFFFFFFFu - (unsigned)e);
        }
        // trans-readout vector
        float trv = 0.f;
        if (tid < BFDIM) {
            int b = tid >> 6, f = tid & 63;
            const float* r = g_rsum + b * FD;
            float s = trb[f];
            const float inv = 1.f / (float)NN;
#pragma unroll 16
            for (int j = 0; j < FD; j++) s += (r[j] * inv) * trw[f * FD + j];
            trv = s;
        }
        __syncthreads();
        if (tid < BFDIM) { g_tr[tid] = trv; g_rsum[tid] = 0.f; }
        __syncthreads();
        if (tid == 0) { g_cnt1 = 0u; g_cnt2 = 0u; g_flagA = 0u; }
    }
}

// -------- scatter by dst (warp per node, high occupancy, alpha via (s,r)) ----------
__global__ __launch_bounds__(256) void k_scatter(const float* __restrict__ x) {
    int tid = threadIdx.x;
    int warp = (blockIdx.x * 256 + tid) >> 5;
    int l = tid & 31;
    if (warp >= NN) return;
    int beg = g_dstPtr[warp], end = g_dstPtr[warp + 1];
    ull th = g_thresh;
    float4 acc = make_float4(0.f, 0.f, 0.f, 0.f);
    int k = beg;
    for (; k + 1 < end; k += 2) {
        uint2 p0 = g_dstPk[k], p1 = g_dstPk[k + 1];
        float a0 = g_alphaNR[(p0.y & 0xFFFFu) * RD + (p0.y >> 16)];
        float a1 = g_alphaNR[(p1.y & 0xFFFFu) * RD + (p1.y >> 16)];
        ull key0 = ((ull)__float_as_uint(a0) << 32) | (unsigned)(0xFFFFFFFFu - p0.x);
        ull key1 = ((ull)__float_as_uint(a1) << 32) | (unsigned)(0xFFFFFFFFu - p1.x);
        if (key0 >= th) {
            float4 xv = __ldg(&reinterpret_cast<const float4*>(x)[(size_t)(p0.y & 0xFFFFu) * 32 + l]);
            float4 rv = reinterpret_cast<const float4*>(g_rel)[(p0.y >> 16) * 32 + l];
            acc.x += a0 * (xv.x + rv.x); acc.y += a0 * (xv.y + rv.y);
            acc.z += a0 * (xv.z + rv.z); acc.w += a0 * (xv.w + rv.w);
        }
        if (key1 >= th) {
            float4 xv = __ldg(&reinterpret_cast<const float4*>(x)[(size_t)(p1.y & 0xFFFFu) * 32 + l]);
            float4 rv = reinterpret_cast<const float4*>(g_rel)[(p1.y >> 16) * 32 + l];
            acc.x += a1 * (xv.x + rv.x); acc.y += a1 * (xv.y + rv.y);
            acc.z += a1 * (xv.z + rv.z); acc.w += a1 * (xv.w + rv.w);
        }
    }
    if (k < end) {
        uint2 p0 = g_dstPk[k];
        float a0 = g_alphaNR[(p0.y & 0xFFFFu) * RD + (p0.y >> 16)];
        ull key0 = ((ull)__float_as_uint(a0) << 32) | (unsigned)(0xFFFFFFFFu - p0.x);
        if (key0 >= th) {
            float4 xv = __ldg(&reinterpret_cast<const float4*>(x)[(size_t)(p0.y & 0xFFFFu) * 32 + l]);
            float4 rv = reinterpret_cast<const float4*>(g_rel)[(p0.y >> 16) * 32 + l];
            acc.x += a0 * (xv.x + rv.x); acc.y += a0 * (xv.y + rv.y);
            acc.z += a0 * (xv.z + rv.z); acc.w += a0 * (xv.w + rv.w);
        }
    }
    reinterpret_cast<float4*>(g_scat)[(size_t)warp * 32 + l] = acc;
}

// ------ fused layer linear + broadcast + LN + ELU + residual + next nx/rsum ----
__global__ __launch_bounds__(512) void k_epi(float* __restrict__ x,
                                             const float* __restrict__ lb,
                                             const float* __restrict__ lng,
                                             const float* __restrict__ lnb,
                                             int it) {
    __shared__ float sWs[FD * FD];
    __shared__ float sW2[FD * FD];
    __shared__ float sTr[BFDIM];
    __shared__ float sWa[BFDIM];
    __shared__ float racc[BFDIM];
    __shared__ float sLb[FD], sG[FD], sB[FD];
    __shared__ float4 sX[32][32];
    __shared__ float4 sS[32][32];
    int tid = threadIdx.x;
    for (int i = tid; i < FD * FD; i += 512) { sWs[i] = g_wsumT[i]; sW2[i] = g_w2T[i]; }
    if (tid < BFDIM) {
        sTr[tid] = g_tr[tid];
        sWa[tid] = (it < 3) ? g_wa[(it + 1) * BFDIM + tid] : 0.f;
        racc[tid] = 0.f;
    }
    if (tid < FD) { sLb[tid] = lb[tid]; sG[tid] = lng[tid]; sB[tid] = lnb[tid]; }
    __syncthreads();
    int w = tid >> 5, l = tid & 31;
    int nbase = blockIdx.x * 32 + w * 2;
    int row0 = w * 2, row1 = w * 2 + 1;
#pragma unroll
    for (int nd = 0; nd < 2; ++nd) {
        int n = nbase + nd;
        sX[row0 + nd][l] = reinterpret_cast<const float4*>(x)[(size_t)n * 32 + l];
        sS[row0 + nd][l] = reinterpret_cast<const float4*>(g_scat)[(size_t)n * 32 + l];
    }
    __syncwarp();

    float acc[2][2][2] = {};
    for (int jv = 0; jv < 16; ++jv) {
        float4 X0a = sX[row0][jv], X1a = sX[row0][16 + jv];
        float4 S0a = sS[row0][jv], S1a = sS[row0][16 + jv];
        float4 X0b = sX[row1][jv], X1b = sX[row1][16 + jv];
        float4 S0b = sS[row1][jv], S1b = sS[row1][16 + jv];
        const float* x0a = (const float*)&X0a; const float* x1a = (const float*)&X1a;
        const float* s0a = (const float*)&S0a; const float* s1a = (const float*)&S1a;
        const float* x0b = (const float*)&X0b; const float* x1b = (const float*)&X1b;
        const float* s0b = (const float*)&S0b; const float* s1b = (const float*)&S1b;
#pragma unroll
        for (int u = 0; u < 4; ++u) {
            int j = jv * 4 + u;
            float wA0 = sWs[j * FD + l], wA1 = sWs[j * FD + 32 + l];
            float wB0 = sW2[j * FD + l], wB1 = sW2[j * FD + 32 + l];
            acc[0][0][0] += x0a[u] * wA0 + s0a[u] * wB0;
            acc[0][0][1] += x0a[u] * wA1 + s0a[u] * wB1;
            acc[0][1][0] += x1a[u] * wA0 + s1a[u] * wB0;
            acc[0][1][1] += x1a[u] * wA1 + s1a[u] * wB1;
            acc[1][0][0] += x0b[u] * wA0 + s0b[u] * wB0;
            acc[1][0][1] += x0b[u] * wA1 + s0b[u] * wB1;
            acc[1][1][0] += x1b[u] * wA0 + s1b[u] * wB0;
            acc[1][1][1] += x1b[u] * wA1 + s1b[u] * wB1;
        }
    }

    const float* sXf = (const float*)sX;
#pragma unroll
    for (int nd = 0; nd < 2; ++nd) {
        int n = nbase + nd;
        int row = row0 + nd;
        float nxacc = 0.f;
#pragma unroll
        for (int b = 0; b < 2; ++b) {
            float v0 = acc[nd][b][0] + sLb[l] + sTr[b * 64 + l];
            float v1 = acc[nd][b][1] + sLb[32 + l] + sTr[b * 64 + 32 + l];
            float s = v0 + v1;
            float q = v0 * v0 + v1 * v1;
#pragma unroll
            for (int o = 16; o; o >>= 1) {
                s += __shfl_xor_sync(0xffffffffu, s, o);
                q += __shfl_xor_sync(0xffffffffu, q, o);
            }
            float mu = s * (1.f / 64.f);
            float var = q * (1.f / 64.f) - mu * mu;
            float rs = rsqrtf(var + 1e-5f);
            v0 = (v0 - mu) * rs * sG[l] + sB[l];
            v1 = (v1 - mu) * rs * sG[32 + l] + sB[32 + l];
            v0 = v0 > 0.f ? v0 : expm1f(v0);
            v1 = v1 > 0.f ? v1 : expm1f(v1);
            float xn0 = v0 + sXf[row * BFDIM + b * 64 + l];
            float xn1 = v1 + sXf[row * BFDIM + b * 64 + 32 + l];
            x[(size_t)n * BFDIM + b * 64 + l] = xn0;
            x[(size_t)n * BFDIM + b * 64 + 32 + l] = xn1;
            if (it < 3) {
                nxacc += xn0 * sWa[b * 64 + l] + xn1 * sWa[b * 64 + 32 + l];
                atomicAdd(&racc[b * 64 + l], xn0);
                atomicAdd(&racc[b * 64 + 32 + l], xn1);
            }
        }
        if (it < 3) {
#pragma unroll
            for (int o = 16; o; o >>= 1) nxacc += __shfl_xor_sync(0xffffffffu, nxacc, o);
            if (l == 0) g_nx[n] = nxacc;
        }
    }
    __syncthreads();
    if (it < 3 && tid < BFDIM) atomicAdd(&g_rsum[tid], racc[tid]);
}

// ---------------- launch ----------------
extern "C" void kernel_launch(void* const* d_in, const int* in_sizes, int n_in,
                              void* d_out, int out_size) {
    const int* ei  = (const int*)d_in[0];
    const int* ri  = (const int*)d_in[1];
    const float* bnd = (const float*)d_in[2];
    const float* qi  = (const float*)d_in[3];
    const float* rw  = (const float*)d_in[4];
    const float* rb  = (const float*)d_in[5];
    const float* lw  = (const float*)d_in[6];
    const float* lb  = (const float*)d_in[7];
    const float* trw = (const float*)d_in[8];
    const float* trb = (const float*)d_in[9];
    const float* Wm  = (const float*)d_in[10];
    const float* av  = (const float*)d_in[11];
    const float* lng = (const float*)d_in[12];
    const float* lnb = (const float*)d_in[13];
    float* x = (float*)d_out;

    static int attr_done = 0;
    static void* srcCntPtr = nullptr;
    static void* dstCntPtr = nullptr;
    static void* cntNRPtr = nullptr;
    if (!attr_done) {
        cudaFuncSetAttribute(k_soft, cudaFuncAttributeMaxDynamicSharedMemorySize, 131072);
        cudaGetSymbolAddress(&srcCntPtr, g_srcCnt);
        cudaGetSymbolAddress(&dstCntPtr, g_dstCnt);
        cudaGetSymbolAddress(&cntNRPtr, g_cntNR);
        attr_done = 1;
    }

    cudaMemsetAsync(srcCntPtr, 0, NN * sizeof(unsigned), 0);
    cudaMemsetAsync(dstCntPtr, 0, NN * sizeof(unsigned), 0);
    cudaMemsetAsync(cntNRPtr, 0, NN * RD * sizeof(unsigned), 0);
    k_prep1<<<34 + 1250, 256>>>(qi, rw, rb, Wm, av, lw, ei);
    k_csr_scan<<<1, 1024>>>();
    k_fill_init<<<1250 + 2500, 256>>>(ei, ri, bnd, x);

    for (int it = 0; it < NITER; ++it) {
        k_soft<<<SB, STH, 131072>>>(it, trw, trb);
        k_scatter<<<2500, 256>>>(x);
        k_epi<<<625, 512>>>(x, lb, lng, lnb, it);
    }
}

// round 12
// speedup vs baseline: 1.1137x; 1.0158x over previous
#include <cuda_runtime.h>
#include <cstdint>
#include <math_constants.h>

#define NN 20000
#define NE 320000
#define BFDIM 128
#define FD 64
#define RD 32
#define KSEL 160000
#define NITER 4
#define SB 148
#define STH 1024

typedef unsigned long long ull;

// ---------------- scratch ----------------
__device__ __align__(16) float g_rel[RD * BFDIM];
__device__ __align__(16) float g_wa[4 * BFDIM];
__device__ float g_drel[4 * RD];
__device__ float g_wsumT[FD * FD];
__device__ float g_w2T[FD * FD];
__device__ float g_tr[BFDIM];
__device__ float g_rsum[BFDIM];
__device__ float g_nx[NN];
__device__ __align__(16) float g_alphaNR[NN * RD];   // per (node, relation) alpha
__device__ __align__(16) unsigned g_cntNR[NN * RD];  // per (node, relation) edge count
__device__ __align__(16) float g_scat[NN * BFDIM];
__device__ __align__(16) unsigned g_fine[256];
__device__ __align__(16) unsigned g_coarse[256];
__device__ unsigned g_cnt1;
__device__ unsigned g_cnt2;
__device__ unsigned g_cnt3;
__device__ unsigned g_flagA;
__device__ unsigned g_flagB;
__device__ unsigned g_c8;
__device__ long long g_remC;
__device__ unsigned g_d0;
__device__ long long g_rem0;
__device__ unsigned g_eqCount;
__device__ int g_eqE[32768];
__device__ unsigned g_eqB[32768];
__device__ ull g_thresh;
// CSR
__device__ int g_srcPtr[NN + 1];
__device__ int g_dstPtr[NN + 1];
__device__ unsigned g_srcCnt[NN];
__device__ unsigned g_dstCnt[NN];
__device__ unsigned g_srcPk[NE];           // e | (r<<19), ordered by src
__device__ __align__(8) uint2 g_dstPk[NE]; // {e, s|(r<<16)}, ordered by dst

// ---------------- prep1: weights + csr count (merged grid) ----------------
__global__ __launch_bounds__(256) void k_prep1(const float* __restrict__ q,
                                               const float* __restrict__ rw,
                                               const float* __restrict__ rb,
                                               const float* __restrict__ Wm,
                                               const float* __restrict__ av,
                                               const float* __restrict__ lw,
                                               const int* __restrict__ ei) {
    if (blockIdx.x < 34) {
        int t = blockIdx.x * blockDim.x + threadIdx.x;
        if (t < 4096) {
            int b = t >> 11, j = t & 2047;
            const float* qr = q + b * FD;
            const float* wr = rw + j * FD;
            float s = rb[j];
#pragma unroll 16
            for (int k = 0; k < FD; k++) s += qr[k] * wr[k];
            g_rel[b * (RD * FD) + j] = s;
        } else if (t < 4608) {
            int u = t - 4096;
            int i = u >> 7, j = u & 127;
            float s = 0.f;
#pragma unroll 16
            for (int f = 0; f < FD; f++) s += Wm[j * FD + f] * av[i * FD + f];
            g_wa[u] = s;
        } else if (t < 8704) {
            int u = t - 4608;
            int j = u >> 6, f = u & 63;
            float w2 = lw[f * 2 * FD + FD + j];
            g_w2T[j * FD + f] = w2;
            g_wsumT[j * FD + f] = lw[f * 2 * FD + j] + w2;
        }
    } else {
        int e = (blockIdx.x - 34) * blockDim.x + threadIdx.x;
        if (e < NE) {
            atomicAdd(&g_srcCnt[ei[e]], 1u);
            atomicAdd(&g_dstCnt[ei[NE + e]], 1u);
        }
    }
}

__global__ __launch_bounds__(1024) void k_csr_scan() {
    __shared__ unsigned ss[1024];
    int t = threadIdx.x;
    if (t < 4 * RD) {
        int i = t >> 5, r = t & 31;
        float s = 0.f;
#pragma unroll 16
        for (int j = 0; j < BFDIM; j++) s += g_rel[r * BFDIM + j] * g_wa[i * BFDIM + j];
        g_drel[t] = s;
    }
    for (int phase = 0; phase < 2; ++phase) {
        unsigned* cnt = phase ? g_dstCnt : g_srcCnt;
        int* ptr = phase ? g_dstPtr : g_srcPtr;
        unsigned loc[20]; unsigned s = 0;
#pragma unroll
        for (int i = 0; i < 20; i++) {
            int idx = t * 20 + i;
            unsigned v = (idx < NN) ? cnt[idx] : 0u;
            loc[i] = s; s += v;
        }
        ss[t] = s;
        __syncthreads();
        for (int off = 1; off < 1024; off <<= 1) {
            unsigned v = (t >= off) ? ss[t - off] : 0u;
            __syncthreads();
            ss[t] += v;
            __syncthreads();
        }
        unsigned base = (t > 0) ? ss[t - 1] : 0u;
#pragma unroll
        for (int i = 0; i < 20; i++) {
            int idx = t * 20 + i;
            if (idx < NN) { ptr[idx] = (int)(base + loc[i]); cnt[idx] = 0u; }
        }
        if (t == 0) ptr[NN] = NE;
        __syncthreads();
    }
}

// ---------------- csr fill (+ per-(n,r) counts) + init (merged grid) ----------------
__global__ __launch_bounds__(256) void k_fill_init(const int* __restrict__ ei,
                                                   const int* __restrict__ ri,
                                                   const float* __restrict__ bnd,
                                                   float* __restrict__ x) {
    int tid = threadIdx.x;
    if (blockIdx.x < 1250) {
        int e = blockIdx.x * 256 + tid;
        if (e >= NE) return;
        int s = ei[e];
        unsigned r = (unsigned)ri[e];
        unsigned p = atomicAdd(&g_srcCnt[s], 1u);
        g_srcPk[g_srcPtr[s] + (int)p] = (unsigned)e | (r << 19);
        atomicAdd(&g_cntNR[s * RD + r], 1u);
        int d = ei[NE + e];
        unsigned p2 = atomicAdd(&g_dstCnt[d], 1u);
        g_dstPk[g_dstPtr[d] + (int)p2] = make_uint2((unsigned)e, (unsigned)s | (r << 16));
    } else {
        __shared__ float racc[BFDIM];
        if (tid < BFDIM) racc[tid] = 0.f;
        __syncthreads();
        int warp = ((blockIdx.x - 1250) * 256 + tid) >> 5;
        int l = tid & 31;
        if (warp < NN) {
            float4 v = reinterpret_cast<const float4*>(bnd)[(size_t)warp * 32 + l];
            reinterpret_cast<float4*>(x)[(size_t)warp * 32 + l] = v;
            float4 w = reinterpret_cast<const float4*>(g_wa)[l];
            float s = v.x * w.x + v.y * w.y + v.z * w.z + v.w * w.w;
#pragma unroll
            for (int o = 16; o; o >>= 1) s += __shfl_xor_sync(0xffffffffu, s, o);
            if (l == 0) g_nx[warp] = s;
            atomicAdd(&racc[l * 4 + 0], v.x);
            atomicAdd(&racc[l * 4 + 1], v.y);
            atomicAdd(&racc[l * 4 + 2], v.z);
            atomicAdd(&racc[l * 4 + 3], v.w);
        }
        __syncthreads();
        if (tid < BFDIM) atomicAdd(&g_rsum[tid], racc[tid]);
    }
}

// ---------------- descending 256-bin pick helper ----------------
__device__ __forceinline__ void pick_desc(unsigned* h, unsigned* sc, int t, long long R,
                                          unsigned* outDigit, long long* outRem) {
    if (t < 256) sc[t] = h[255 - t];
    __syncthreads();
    for (int off = 1; off < 256; off <<= 1) {
        unsigned v = (t < 256 && t >= off) ? sc[t - off] : 0u;
        __syncthreads();
        if (t < 256) sc[t] += v;
        __syncthreads();
    }
    if (t < 256) {
        long long incl = (long long)sc[t];
        long long before = incl - (long long)h[255 - t];
        if (before < R && R <= incl) { *outDigit = (unsigned)(255 - t); *outRem = R - before; }
    }
    __syncthreads();
}

// ==== persistent fused: (n,r)-softmax + 3-level hierarchical pick + resolve + tr ====
__global__ __launch_bounds__(STH) void k_soft(int it, const float* __restrict__ trw,
                                              const float* __restrict__ trb) {
    __shared__ unsigned chist[256];
    __shared__ unsigned hh[256], hsc[256];
    __shared__ unsigned selDigit; __shared__ long long selRem;
    __shared__ unsigned isLast, candCnt;
    __shared__ int cand[4096];
    int tid = threadIdx.x;
    int l = tid & 31;
    if (tid < 256) chist[tid] = 0u;
    __syncthreads();
    float dr = g_drel[it * RD + l];
    int warp = blockIdx.x * (STH / 32) + (tid >> 5);
    int totalWarps = SB * (STH / 32);
    // ---- P1: warp per node, lane = relation; coarse (top-8) hist ----
    for (int n = warp; n < NN; n += totalWarps) {
        unsigned c = g_cntNR[n * RD + l];
        bool valid = (c != 0u);
        unsigned vm = __ballot_sync(0xffffffffu, valid);
        if (vm == 0u) { g_alphaNR[n * RD + l] = 0.f; continue; }
        float nx = g_nx[n];
        float t = nx + dr;
        t = t > 0.f ? t : 0.2f * t;
        float m = valid ? t : -CUDART_INF_F;
#pragma unroll
        for (int o = 16; o; o >>= 1) m = fmaxf(m, __shfl_xor_sync(0xffffffffu, m, o));
        float ex = valid ? expf(t - m) : 0.f;
        float cs = (float)c * ex;
#pragma unroll
        for (int o = 16; o; o >>= 1) cs += __shfl_xor_sync(0xffffffffu, cs, o);
        float a = ex * (1.f / (cs + 1e-16f));
        g_alphaNR[n * RD + l] = a;
        if (valid) atomicAdd(&chist[__float_as_uint(a) >> 24], c);
    }
    __syncthreads();
    if (tid < 256 && chist[tid]) atomicAdd(&g_coarse[tid], chist[tid]);
    __threadfence();
    // ---- R1: pick coarse ----
    if (tid == 0) isLast = (atomicAdd(&g_cnt1, 1u) == gridDim.x - 1u) ? 1u : 0u;
    __syncthreads();
    if (isLast) {
        if (tid < 256) hh[tid] = g_coarse[tid];
        __syncthreads();
        pick_desc(hh, hsc, tid, (long long)KSEL, &selDigit, &selRem);
        if (tid == 0) { g_c8 = selDigit; g_remC = selRem; }
        if (tid < 256) g_coarse[tid] = 0u;
        __threadfence();
        __syncthreads();
        if (tid == 0) atomicExch(&g_flagA, 1u);
    } else {
        if (tid == 0) { while (atomicAdd(&g_flagA, 0u) == 0u) { __nanosleep(64); } }
        __syncthreads();
        __threadfence();
    }
    // ---- P2: fine hist (bits[16:24)) over matching (n,r) ----
    __syncthreads();
    if (tid < 256) chist[tid] = 0u;
    __syncthreads();
    unsigned c8 = g_c8;
    for (int i = blockIdx.x * STH + tid; i < NN * RD; i += SB * STH) {
        unsigned bits = __float_as_uint(g_alphaNR[i]);
        if ((bits >> 24) == c8 && bits != 0u)
            atomicAdd(&chist[(bits >> 16) & 0xFFu], g_cntNR[i]);
    }
    __syncthreads();
    if (tid < 256 && chist[tid]) atomicAdd(&g_fine[tid], chist[tid]);
    __threadfence();
    // ---- R2: pick fine -> d0 ----
    if (tid == 0) isLast = (atomicAdd(&g_cnt2, 1u) == gridDim.x - 1u) ? 1u : 0u;
    __syncthreads();
    if (isLast) {
        if (tid < 256) hh[tid] = g_fine[tid];
        __syncthreads();
        pick_desc(hh, hsc, tid, g_remC, &selDigit, &selRem);
        if (tid == 0) {
            g_d0 = (c8 << 8) | selDigit;
            g_rem0 = selRem;
            g_eqCount = 0u;
        }
        if (tid < 256) g_fine[tid] = 0u;
        __threadfence();
        __syncthreads();
        if (tid == 0) atomicExch(&g_flagB, 1u);
    } else {
        if (tid == 0) { while (atomicAdd(&g_flagB, 0u) == 0u) { __nanosleep(64); } }
        __syncthreads();
        __threadfence();
    }
    // ---- P3: collect bucket d0 (warp per node, early-out ballot) ----
    {
        unsigned d0 = g_d0;
        for (int n = warp; n < NN; n += totalWarps) {
            float a = g_alphaNR[n * RD + l];
            unsigned bits = __float_as_uint(a);
            unsigned match = __ballot_sync(0xffffffffu, (bits >> 16) == d0 && bits != 0u);
            if (match == 0u) continue;
            int beg = g_srcPtr[n], end = g_srcPtr[n + 1];
            for (int k0 = beg; k0 < end; k0 += 32) {
                int k = k0 + l;
                bool act = (k < end);
                unsigned pk = act ? g_srcPk[k] : 0u;
                unsigned r = pk >> 19;
                unsigned br = __shfl_sync(0xffffffffu, bits, (int)r);
                if (act && ((match >> r) & 1u)) {
                    unsigned p = atomicAdd(&g_eqCount, 1u);
                    if (p < 32768u) { g_eqE[p] = (int)(pk & 0x7FFFFu); g_eqB[p] = br; }
                }
            }
        }
    }
    __threadfence();
    if (tid == 0) isLast = (atomicAdd(&g_cnt3, 1u) == gridDim.x - 1u) ? 1u : 0u;
    __syncthreads();
    if (!isLast) return;
    // ---- last block: resolve + tr vector + reset sync state ----
    {
        int c = (int)min(g_eqCount, 32768u);
        long long r0 = g_rem0;
        unsigned d0 = g_d0;
        if (tid < 256) hh[tid] = 0u;
        __syncthreads();
        for (int i = tid; i < c; i += STH) atomicAdd(&hh[(g_eqB[i] >> 8) & 0xFFu], 1u);
        __syncthreads();
        pick_desc(hh, hsc, tid, r0, &selDigit, &selRem);
        unsigned b1 = selDigit; long long r1 = selRem;
        if (tid < 256) hh[tid] = 0u;
        __syncthreads();
        for (int i = tid; i < c; i += STH) {
            unsigned bits = g_eqB[i];
            if (((bits >> 8) & 0xFFu) == b1) atomicAdd(&hh[bits & 0xFFu], 1u);
        }
        __syncthreads();
        pick_desc(hh, hsc, tid, r1, &selDigit, &selRem);
        unsigned T = (d0 << 16) | (b1 << 8) | selDigit;
        int r2 = (int)selRem;
        if (tid == 0) candCnt = 0u;
        __syncthreads();
        for (int i = tid; i < c; i += STH) {
            if (g_eqB[i] == T) {
                unsigned p = atomicAdd(&candCnt, 1u);
                if (p < 4096u) cand[p] = g_eqE[i];
            }
        }
        __syncthreads();
        int tc2 = (int)min(candCnt, 4096u);
        for (int i = tid; i < tc2; i += STH) {
            int e = cand[i];
            int cnt = 0;
            for (int j = 0; j < tc2; ++j) cnt += (cand[j] < e) ? 1 : 0;
            if (cnt == r2 - 1)
                g_thresh = ((ull)T << 32) | (unsigned)(0xFFFFFFFFu - (unsigned)e);
        }
        // trans-readout vector
        float trv = 0.f;
        if (tid < BFDIM) {
            int b = tid >> 6, f = tid & 63;
            const float* r = g_rsum + b * FD;
            float s = trb[f];
            const float inv = 1.f / (float)NN;
#pragma unroll 16
            for (int j = 0; j < FD; j++) s += (r[j] * inv) * trw[f * FD + j];
            trv = s;
        }
        __syncthreads();
        if (tid < BFDIM) { g_tr[tid] = trv; g_rsum[tid] = 0.f; }
        __syncthreads();
        if (tid == 0) {
            g_cnt1 = 0u; g_cnt2 = 0u; g_cnt3 = 0u;
            g_flagA = 0u; g_flagB = 0u;
        }
    }
}

// -------- scatter by dst (warp per node, high occupancy, alpha via (s,r)) ----------
__global__ __launch_bounds__(256) void k_scatter(const float* __restrict__ x) {
    int tid = threadIdx.x;
    int warp = (blockIdx.x * 256 + tid) >> 5;
    int l = tid & 31;
    if (warp >= NN) return;
    int beg = g_dstPtr[warp], end = g_dstPtr[warp + 1];
    ull th = g_thresh;
    float4 acc = make_float4(0.f, 0.f, 0.f, 0.f);
    int k = beg;
    for (; k + 1 < end; k += 2) {
        uint2 p0 = g_dstPk[k], p1 = g_dstPk[k + 1];
        float a0 = g_alphaNR[(p0.y & 0xFFFFu) * RD + (p0.y >> 16)];
        float a1 = g_alphaNR[(p1.y & 0xFFFFu) * RD + (p1.y >> 16)];
        ull key0 = ((ull)__float_as_uint(a0) << 32) | (unsigned)(0xFFFFFFFFu - p0.x);
        ull key1 = ((ull)__float_as_uint(a1) << 32) | (unsigned)(0xFFFFFFFFu - p1.x);
        if (key0 >= th) {
            float4 xv = __ldg(&reinterpret_cast<const float4*>(x)[(size_t)(p0.y & 0xFFFFu) * 32 + l]);
            float4 rv = reinterpret_cast<const float4*>(g_rel)[(p0.y >> 16) * 32 + l];
            acc.x += a0 * (xv.x + rv.x); acc.y += a0 * (xv.y + rv.y);
            acc.z += a0 * (xv.z + rv.z); acc.w += a0 * (xv.w + rv.w);
        }
        if (key1 >= th) {
            float4 xv = __ldg(&reinterpret_cast<const float4*>(x)[(size_t)(p1.y & 0xFFFFu) * 32 + l]);
            float4 rv = reinterpret_cast<const float4*>(g_rel)[(p1.y >> 16) * 32 + l];
            acc.x += a1 * (xv.x + rv.x); acc.y += a1 * (xv.y + rv.y);
            acc.z += a1 * (xv.z + rv.z); acc.w += a1 * (xv.w + rv.w);
        }
    }
    if (k < end) {
        uint2 p0 = g_dstPk[k];
        float a0 = g_alphaNR[(p0.y & 0xFFFFu) * RD + (p0.y >> 16)];
        ull key0 = ((ull)__float_as_uint(a0) << 32) | (unsigned)(0xFFFFFFFFu - p0.x);
        if (key0 >= th) {
            float4 xv = __ldg(&reinterpret_cast<const float4*>(x)[(size_t)(p0.y & 0xFFFFu) * 32 + l]);
            float4 rv = reinterpret_cast<const float4*>(g_rel)[(p0.y >> 16) * 32 + l];
            acc.x += a0 * (xv.x + rv.x); acc.y += a0 * (xv.y + rv.y);
            acc.z += a0 * (xv.z + rv.z); acc.w += a0 * (xv.w + rv.w);
        }
    }
    reinterpret_cast<float4*>(g_scat)[(size_t)warp * 32 + l] = acc;
}

// ------ fused layer linear + broadcast + LN + ELU + residual + next nx/rsum ----
__global__ __launch_bounds__(512) void k_epi(float* __restrict__ x,
                                             const float* __restrict__ lb,
                                             const float* __restrict__ lng,
                                             const float* __restrict__ lnb,
                                             int it) {
    __shared__ float sWs[FD * FD];
    __shared__ float sW2[FD * FD];
    __shared__ float sTr[BFDIM];
    __shared__ float sWa[BFDIM];
    __shared__ float racc[BFDIM];
    __shared__ float sLb[FD], sG[FD], sB[FD];
    __shared__ float4 sX[32][32];
    __shared__ float4 sS[32][32];
    int tid = threadIdx.x;
    for (int i = tid; i < FD * FD; i += 512) { sWs[i] = g_wsumT[i]; sW2[i] = g_w2T[i]; }
    if (tid < BFDIM) {
        sTr[tid] = g_tr[tid];
        sWa[tid] = (it < 3) ? g_wa[(it + 1) * BFDIM + tid] : 0.f;
        racc[tid] = 0.f;
    }
    if (tid < FD) { sLb[tid] = lb[tid]; sG[tid] = lng[tid]; sB[tid] = lnb[tid]; }
    __syncthreads();
    int w = tid >> 5, l = tid & 31;
    int nbase = blockIdx.x * 32 + w * 2;
    int row0 = w * 2, row1 = w * 2 + 1;
#pragma unroll
    for (int nd = 0; nd < 2; ++nd) {
        int n = nbase + nd;
        sX[row0 + nd][l] = reinterpret_cast<const float4*>(x)[(size_t)n * 32 + l];
        sS[row0 + nd][l] = reinterpret_cast<const float4*>(g_scat)[(size_t)n * 32 + l];
    }
    __syncwarp();

    float acc[2][2][2] = {};
    for (int jv = 0; jv < 16; ++jv) {
        float4 X0a = sX[row0][jv], X1a = sX[row0][16 + jv];
        float4 S0a = sS[row0][jv], S1a = sS[row0][16 + jv];
        float4 X0b = sX[row1][jv], X1b = sX[row1][16 + jv];
        float4 S0b = sS[row1][jv], S1b = sS[row1][16 + jv];
        const float* x0a = (const float*)&X0a; const float* x1a = (const float*)&X1a;
        const float* s0a = (const float*)&S0a; const float* s1a = (const float*)&S1a;
        const float* x0b = (const float*)&X0b; const float* x1b = (const float*)&X1b;
        const float* s0b = (const float*)&S0b; const float* s1b = (const float*)&S1b;
#pragma unroll
        for (int u = 0; u < 4; ++u) {
            int j = jv * 4 + u;
            float wA0 = sWs[j * FD + l], wA1 = sWs[j * FD + 32 + l];
            float wB0 = sW2[j * FD + l], wB1 = sW2[j * FD + 32 + l];
            acc[0][0][0] += x0a[u] * wA0 + s0a[u] * wB0;
            acc[0][0][1] += x0a[u] * wA1 + s0a[u] * wB1;
            acc[0][1][0] += x1a[u] * wA0 + s1a[u] * wB0;
            acc[0][1][1] += x1a[u] * wA1 + s1a[u] * wB1;
            acc[1][0][0] += x0b[u] * wA0 + s0b[u] * wB0;
            acc[1][0][1] += x0b[u] * wA1 + s0b[u] * wB1;
            acc[1][1][0] += x1b[u] * wA0 + s1b[u] * wB0;
            acc[1][1][1] += x1b[u] * wA1 + s1b[u] * wB1;
        }
    }

    const float* sXf = (const float*)sX;
#pragma unroll
    for (int nd = 0; nd < 2; ++nd) {
        int n = nbase + nd;
        int row = row0 + nd;
        float nxacc = 0.f;
#pragma unroll
        for (int b = 0; b < 2; ++b) {
            float v0 = acc[nd][b][0] + sLb[l] + sTr[b * 64 + l];
            float v1 = acc[nd][b][1] + sLb[32 + l] + sTr[b * 64 + 32 + l];
            float s = v0 + v1;
            float q = v0 * v0 + v1 * v1;
#pragma unroll
            for (int o = 16; o; o >>= 1) {
                s += __shfl_xor_sync(0xffffffffu, s, o);
                q += __shfl_xor_sync(0xffffffffu, q, o);
            }
            float mu = s * (1.f / 64.f);
            float var = q * (1.f / 64.f) - mu * mu;
            float rs = rsqrtf(var + 1e-5f);
            v0 = (v0 - mu) * rs * sG[l] + sB[l];
            v1 = (v1 - mu) * rs * sG[32 + l] + sB[32 + l];
            v0 = v0 > 0.f ? v0 : expm1f(v0);
            v1 = v1 > 0.f ? v1 : expm1f(v1);
            float xn0 = v0 + sXf[row * BFDIM + b * 64 + l];
            float xn1 = v1 + sXf[row * BFDIM + b * 64 + 32 + l];
            x[(size_t)n * BFDIM + b * 64 + l] = xn0;
            x[(size_t)n * BFDIM + b * 64 + 32 + l] = xn1;
            if (it < 3) {
                nxacc += xn0 * sWa[b * 64 + l] + xn1 * sWa[b * 64 + 32 + l];
                atomicAdd(&racc[b * 64 + l], xn0);
                atomicAdd(&racc[b * 64 + 32 + l], xn1);
            }
        }
        if (it < 3) {
#pragma unroll
            for (int o = 16; o; o >>= 1) nxacc += __shfl_xor_sync(0xffffffffu, nxacc, o);
            if (l == 0) g_nx[n] = nxacc;
        }
    }
    __syncthreads();
    if (it < 3 && tid < BFDIM) atomicAdd(&g_rsum[tid], racc[tid]);
    // last iteration: reset counters for next graph replay (globals are 0-init first run)
    if (it == 3) {
        int gid = blockIdx.x * 512 + tid;            // 0 .. 319999
        for (int i = gid; i < NN * RD; i += 625 * 512) g_cntNR[i] = 0u;
        if (gid < NN) { g_srcCnt[gid] = 0u; g_dstCnt[gid] = 0u; }
    }
}

// ---------------- launch ----------------
extern "C" void kernel_launch(void* const* d_in, const int* in_sizes, int n_in,
                              void* d_out, int out_size) {
    const int* ei  = (const int*)d_in[0];
    const int* ri  = (const int*)d_in[1];
    const float* bnd = (const float*)d_in[2];
    const float* qi  = (const float*)d_in[3];
    const float* rw  = (const float*)d_in[4];
    const float* rb  = (const float*)d_in[5];
    const float* lw  = (const float*)d_in[6];
    const float* lb  = (const float*)d_in[7];
    const float* trw = (const float*)d_in[8];
    const float* trb = (const float*)d_in[9];
    const float* Wm  = (const float*)d_in[10];
    const float* av  = (const float*)d_in[11];
    const float* lng = (const float*)d_in[12];
    const float* lnb = (const float*)d_in[13];
    float* x = (float*)d_out;

    k_prep1<<<34 + 1250, 256>>>(qi, rw, rb, Wm, av, lw, ei);
    k_csr_scan<<<1, 1024>>>();
    k_fill_init<<<1250 + 2500, 256>>>(ei, ri, bnd, x);

    for (int it = 0; it < NITER; ++it) {
        k_soft<<<SB, STH>>>(it, trw, trb);
        k_scatter<<<2500, 256>>>(x);
        k_epi<<<625, 512>>>(x, lb, lng, lnb, it);
    }
}

// round 14
// speedup vs baseline: 1.1979x; 1.0757x over previous
#include <cuda_runtime.h>
#include <cstdint>
#include <math_constants.h>

#define NN 20000
#define NE 320000
#define BFDIM 128
#define FD 64
#define RD 32
#define KSEL 160000
#define NITER 4
#define SB 148
#define STH 1024

typedef unsigned long long ull;

// ---------------- scratch ----------------
__device__ __align__(16) float g_rel[RD * BFDIM];
__device__ __align__(16) float g_wa[4 * BFDIM];
__device__ float g_drel[4 * RD];
__device__ float g_wsumT[FD * FD];
__device__ float g_w2T[FD * FD];
__device__ float g_tr[BFDIM];
__device__ float g_rsum[BFDIM];
__device__ float g_nx[NN];
__device__ __align__(16) float g_alphaNR[NN * RD];
__device__ __align__(16) unsigned g_cntNR[NN * RD];
__device__ __align__(16) float g_scat[NN * BFDIM];
__device__ __align__(16) unsigned g_fine[256];
__device__ __align__(16) unsigned g_coarse[256];
__device__ unsigned g_cnt1;
__device__ unsigned g_cnt2;
__device__ unsigned g_cnt3;
__device__ unsigned g_flagA;
__device__ unsigned g_flagB;
__device__ unsigned g_c8;
__device__ long long g_remC;
__device__ unsigned g_d0;
__device__ long long g_rem0;
__device__ unsigned g_eqCount;
__device__ int g_eqE[32768];
__device__ unsigned g_eqB[32768];
__device__ ull g_thresh;
// CSR
__device__ int g_srcPtr[NN + 1];
__device__ int g_dstPtr[NN + 1];
__device__ unsigned g_srcCnt[NN];
__device__ unsigned g_dstCnt[NN];
__device__ unsigned g_srcPk[NE];
__device__ __align__(8) uint2 g_dstPk[NE];

// ---------------- f32x2 helpers ----------------
__device__ __forceinline__ ull fdup(float x) {
    ull r; asm("mov.b64 %0,{%1,%1};" : "=l"(r) : "f"(x)); return r;
}
__device__ __forceinline__ ull fpack(float a, float b) {
    ull r; asm("mov.b64 %0,{%1,%2};" : "=l"(r) : "f"(a), "f"(b)); return r;
}
__device__ __forceinline__ void ffma2(ull& acc, ull w, ull x) {
    asm("fma.rn.f32x2 %0,%1,%2,%0;" : "+l"(acc) : "l"(w), "l"(x));
}
__device__ __forceinline__ void funpack(ull p, float& lo, float& hi) {
    asm("mov.b64 {%0,%1},%2;" : "=f"(lo), "=f"(hi) : "l"(p));
}

// ---------------- prep1 ----------------
__global__ __launch_bounds__(256) void k_prep1(const float* __restrict__ q,
                                               const float* __restrict__ rw,
                                               const float* __restrict__ rb,
                                               const float* __restrict__ Wm,
                                               const float* __restrict__ av,
                                               const float* __restrict__ lw,
                                               const int* __restrict__ ei) {
    if (blockIdx.x < 34) {
        int t = blockIdx.x * blockDim.x + threadIdx.x;
        if (t < 4096) {
            int b = t >> 11, j = t & 2047;
            const float* qr = q + b * FD;
            const float* wr = rw + j * FD;
            float s = rb[j];
#pragma unroll 16
            for (int k = 0; k < FD; k++) s += qr[k] * wr[k];
            g_rel[b * (RD * FD) + j] = s;
        } else if (t < 4608) {
            int u = t - 4096;
            int i = u >> 7, j = u & 127;
            float s = 0.f;
#pragma unroll 16
            for (int f = 0; f < FD; f++) s += Wm[j * FD + f] * av[i * FD + f];
            g_wa[u] = s;
        } else if (t < 8704) {
            int u = t - 4608;
            int j = u >> 6, f = u & 63;
            float w2 = lw[f * 2 * FD + FD + j];
            g_w2T[j * FD + f] = w2;
            g_wsumT[j * FD + f] = lw[f * 2 * FD + j] + w2;
        }
    } else {
        int e = (blockIdx.x - 34) * blockDim.x + threadIdx.x;
        if (e < NE) {
            atomicAdd(&g_srcCnt[ei[e]], 1u);
            atomicAdd(&g_dstCnt[ei[NE + e]], 1u);
        }
    }
}

__global__ __launch_bounds__(1024) void k_csr_scan() {
    __shared__ unsigned ss[1024];
    int t = threadIdx.x;
    if (t < 4 * RD) {
        int i = t >> 5, r = t & 31;
        float s = 0.f;
#pragma unroll 16
        for (int j = 0; j < BFDIM; j++) s += g_rel[r * BFDIM + j] * g_wa[i * BFDIM + j];
        g_drel[t] = s;
    }
    for (int phase = 0; phase < 2; ++phase) {
        unsigned* cnt = phase ? g_dstCnt : g_srcCnt;
        int* ptr = phase ? g_dstPtr : g_srcPtr;
        unsigned loc[20]; unsigned s = 0;
#pragma unroll
        for (int i = 0; i < 20; i++) {
            int idx = t * 20 + i;
            unsigned v = (idx < NN) ? cnt[idx] : 0u;
            loc[i] = s; s += v;
        }
        ss[t] = s;
        __syncthreads();
        for (int off = 1; off < 1024; off <<= 1) {
            unsigned v = (t >= off) ? ss[t - off] : 0u;
            __syncthreads();
            ss[t] += v;
            __syncthreads();
        }
        unsigned base = (t > 0) ? ss[t - 1] : 0u;
#pragma unroll
        for (int i = 0; i < 20; i++) {
            int idx = t * 20 + i;
            if (idx < NN) { ptr[idx] = (int)(base + loc[i]); cnt[idx] = 0u; }
        }
        if (t == 0) ptr[NN] = NE;
        __syncthreads();
    }
}

// ---------------- csr fill + init ----------------
__global__ __launch_bounds__(256) void k_fill_init(const int* __restrict__ ei,
                                                   const int* __restrict__ ri,
                                                   const float* __restrict__ bnd,
                                                   float* __restrict__ x) {
    int tid = threadIdx.x;
    if (blockIdx.x < 1250) {
        int e = blockIdx.x * 256 + tid;
        if (e >= NE) return;
        int s = ei[e];
        unsigned r = (unsigned)ri[e];
        unsigned p = atomicAdd(&g_srcCnt[s], 1u);
        g_srcPk[g_srcPtr[s] + (int)p] = (unsigned)e | (r << 19);
        atomicAdd(&g_cntNR[s * RD + r], 1u);
        int d = ei[NE + e];
        unsigned p2 = atomicAdd(&g_dstCnt[d], 1u);
        g_dstPk[g_dstPtr[d] + (int)p2] = make_uint2((unsigned)e, (unsigned)s | (r << 16));
    } else {
        __shared__ float racc[BFDIM];
        if (tid < BFDIM) racc[tid] = 0.f;
        __syncthreads();
        int warp = ((blockIdx.x - 1250) * 256 + tid) >> 5;
        int l = tid & 31;
        if (warp < NN) {
            float4 v = reinterpret_cast<const float4*>(bnd)[(size_t)warp * 32 + l];
            reinterpret_cast<float4*>(x)[(size_t)warp * 32 + l] = v;
            float4 w = reinterpret_cast<const float4*>(g_wa)[l];
            float s = v.x * w.x + v.y * w.y + v.z * w.z + v.w * w.w;
#pragma unroll
            for (int o = 16; o; o >>= 1) s += __shfl_xor_sync(0xffffffffu, s, o);
            if (l == 0) g_nx[warp] = s;
            atomicAdd(&racc[l * 4 + 0], v.x);
            atomicAdd(&racc[l * 4 + 1], v.y);
            atomicAdd(&racc[l * 4 + 2], v.z);
            atomicAdd(&racc[l * 4 + 3], v.w);
        }
        __syncthreads();
        if (tid < BFDIM) atomicAdd(&g_rsum[tid], racc[tid]);
    }
}

// ---------------- descending 256-bin pick helper ----------------
__device__ __forceinline__ void pick_desc(unsigned* h, unsigned* sc, int t, long long R,
                                          unsigned* outDigit, long long* outRem) {
    if (t < 256) sc[t] = h[255 - t];
    __syncthreads();
    for (int off = 1; off < 256; off <<= 1) {
        unsigned v = (t < 256 && t >= off) ? sc[t - off] : 0u;
        __syncthreads();
        if (t < 256) sc[t] += v;
        __syncthreads();
    }
    if (t < 256) {
        long long incl = (long long)sc[t];
        long long before = incl - (long long)h[255 - t];
        if (before < R && R <= incl) { *outDigit = (unsigned)(255 - t); *outRem = R - before; }
    }
    __syncthreads();
}

// ==== persistent: [it==0: P1] + pick + fine + pick + collect + resolve + tr ====
__global__ __launch_bounds__(STH) void k_soft(int it, const float* __restrict__ trw,
                                              const float* __restrict__ trb) {
    __shared__ unsigned chist[256];
    __shared__ unsigned hh[256], hsc[256];
    __shared__ unsigned selDigit; __shared__ long long selRem;
    __shared__ unsigned isLast, candCnt, doPickS;
    __shared__ int cand[4096];
    int tid = threadIdx.x;
    int l = tid & 31;
    int warp = blockIdx.x * (STH / 32) + (tid >> 5);
    int totalWarps = SB * (STH / 32);

    if (it == 0) {
        if (tid < 256) chist[tid] = 0u;
        __syncthreads();
        float dr = g_drel[l];
        for (int n = warp; n < NN; n += totalWarps) {
            unsigned c = g_cntNR[n * RD + l];
            bool valid = (c != 0u);
            unsigned vm = __ballot_sync(0xffffffffu, valid);
            if (vm == 0u) { g_alphaNR[n * RD + l] = 0.f; continue; }
            float nx = g_nx[n];
            float t = nx + dr;
            t = t > 0.f ? t : 0.2f * t;
            float m = valid ? t : -CUDART_INF_F;
#pragma unroll
            for (int o = 16; o; o >>= 1) m = fmaxf(m, __shfl_xor_sync(0xffffffffu, m, o));
            float ex = valid ? expf(t - m) : 0.f;
            float cs = (float)c * ex;
#pragma unroll
            for (int o = 16; o; o >>= 1) cs += __shfl_xor_sync(0xffffffffu, cs, o);
            float a = ex * (1.f / (cs + 1e-16f));
            g_alphaNR[n * RD + l] = a;
            if (valid) atomicAdd(&chist[__float_as_uint(a) >> 24], c);
        }
        __syncthreads();
        if (tid < 256 && chist[tid]) atomicAdd(&g_coarse[tid], chist[tid]);
        __threadfence();
        if (tid == 0) doPickS = (atomicAdd(&g_cnt1, 1u) == gridDim.x - 1u) ? 1u : 0u;
        __syncthreads();
    } else {
        if (tid == 0) doPickS = (blockIdx.x == 0) ? 1u : 0u;
        __syncthreads();
    }
    // ---- R1: pick coarse ----
    if (doPickS) {
        if (tid < 256) hh[tid] = g_coarse[tid];
        __syncthreads();
        pick_desc(hh, hsc, tid, (long long)KSEL, &selDigit, &selRem);
        if (tid == 0) { g_c8 = selDigit; g_remC = selRem; }
        if (tid < 256) g_coarse[tid] = 0u;
        __threadfence();
        __syncthreads();
        if (tid == 0) atomicExch(&g_flagA, 1u);
    } else {
        if (tid == 0) { while (atomicAdd(&g_flagA, 0u) == 0u) { __nanosleep(64); } }
        __syncthreads();
        __threadfence();
    }
    // ---- P2: fine hist over matching (n,r) ----
    __syncthreads();
    if (tid < 256) chist[tid] = 0u;
    __syncthreads();
    unsigned c8 = g_c8;
    for (int i = blockIdx.x * STH + tid; i < NN * RD; i += SB * STH) {
        unsigned bits = __float_as_uint(g_alphaNR[i]);
        if ((bits >> 24) == c8 && bits != 0u)
            atomicAdd(&chist[(bits >> 16) & 0xFFu], g_cntNR[i]);
    }
    __syncthreads();
    if (tid < 256 && chist[tid]) atomicAdd(&g_fine[tid], chist[tid]);
    __threadfence();
    if (tid == 0) isLast = (atomicAdd(&g_cnt2, 1u) == gridDim.x - 1u) ? 1u : 0u;
    __syncthreads();
    if (isLast) {
        if (tid < 256) hh[tid] = g_fine[tid];
        __syncthreads();
        pick_desc(hh, hsc, tid, g_remC, &selDigit, &selRem);
        if (tid == 0) {
            g_d0 = (c8 << 8) | selDigit;
            g_rem0 = selRem;
            g_eqCount = 0u;
        }
        if (tid < 256) g_fine[tid] = 0u;
        __threadfence();
        __syncthreads();
        if (tid == 0) atomicExch(&g_flagB, 1u);
    } else {
        if (tid == 0) { while (atomicAdd(&g_flagB, 0u) == 0u) { __nanosleep(64); } }
        __syncthreads();
        __threadfence();
    }
    // ---- P3: collect bucket d0 ----
    {
        unsigned d0 = g_d0;
        for (int n = warp; n < NN; n += totalWarps) {
            float a = g_alphaNR[n * RD + l];
            unsigned bits = __float_as_uint(a);
            unsigned match = __ballot_sync(0xffffffffu, (bits >> 16) == d0 && bits != 0u);
            if (match == 0u) continue;
            int beg = g_srcPtr[n], end = g_srcPtr[n + 1];
            for (int k0 = beg; k0 < end; k0 += 32) {
                int k = k0 + l;
                bool act = (k < end);
                unsigned pk = act ? g_srcPk[k] : 0u;
                unsigned r = pk >> 19;
                unsigned br = __shfl_sync(0xffffffffu, bits, (int)r);
                if (act && ((match >> r) & 1u)) {
                    unsigned p = atomicAdd(&g_eqCount, 1u);
                    if (p < 32768u) { g_eqE[p] = (int)(pk & 0x7FFFFu); g_eqB[p] = br; }
                }
            }
        }
    }
    __threadfence();
    if (tid == 0) isLast = (atomicAdd(&g_cnt3, 1u) == gridDim.x - 1u) ? 1u : 0u;
    __syncthreads();
    if (!isLast) return;
    // ---- last block: resolve + tr vector + reset ----
    {
        int c = (int)min(g_eqCount, 32768u);
        long long r0 = g_rem0;
        unsigned d0 = g_d0;
        if (tid < 256) hh[tid] = 0u;
        __syncthreads();
        for (int i = tid; i < c; i += STH) atomicAdd(&hh[(g_eqB[i] >> 8) & 0xFFu], 1u);
        __syncthreads();
        pick_desc(hh, hsc, tid, r0, &selDigit, &selRem);
        unsigned b1 = selDigit; long long r1 = selRem;
        if (tid < 256) hh[tid] = 0u;
        __syncthreads();
        for (int i = tid; i < c; i += STH) {
            unsigned bits = g_eqB[i];
            if (((bits >> 8) & 0xFFu) == b1) atomicAdd(&hh[bits & 0xFFu], 1u);
        }
        __syncthreads();
        pick_desc(hh, hsc, tid, r1, &selDigit, &selRem);
        unsigned T = (d0 << 16) | (b1 << 8) | selDigit;
        int r2 = (int)selRem;
        if (tid == 0) candCnt = 0u;
        __syncthreads();
        for (int i = tid; i < c; i += STH) {
            if (g_eqB[i] == T) {
                unsigned p = atomicAdd(&candCnt, 1u);
                if (p < 4096u) cand[p] = g_eqE[i];
            }
        }
        __syncthreads();
        int tc2 = (int)min(candCnt, 4096u);
        for (int i = tid; i < tc2; i += STH) {
            int e = cand[i];
            int cnt = 0;
            for (int j = 0; j < tc2; ++j) cnt += (cand[j] < e) ? 1 : 0;
            if (cnt == r2 - 1)
                g_thresh = ((ull)T << 32) | (unsigned)(0xFFFFFFFFu - (unsigned)e);
        }
        float trv = 0.f;
        if (tid < BFDIM) {
            int b = tid >> 6, f = tid & 63;
            const float* r = g_rsum + b * FD;
            float s = trb[f];
            const float inv = 1.f / (float)NN;
#pragma unroll 16
            for (int j = 0; j < FD; j++) s += (r[j] * inv) * trw[f * FD + j];
            trv = s;
        }
        __syncthreads();
        if (tid < BFDIM) { g_tr[tid] = trv; g_rsum[tid] = 0.f; }
        __syncthreads();
        if (tid == 0) {
            g_cnt1 = 0u; g_cnt2 = 0u; g_cnt3 = 0u;
            g_flagA = 0u; g_flagB = 0u;
        }
    }
}

// -------- scatter by dst (warp per node, high occupancy) ----------
__global__ __launch_bounds__(256) void k_scatter(const float* __restrict__ x) {
    int tid = threadIdx.x;
    int warp = (blockIdx.x * 256 + tid) >> 5;
    int l = tid & 31;
    if (warp >= NN) return;
    int beg = g_dstPtr[warp], end = g_dstPtr[warp + 1];
    ull th = g_thresh;
    float4 acc = make_float4(0.f, 0.f, 0.f, 0.f);
    int k = beg;
    for (; k + 1 < end; k += 2) {
        uint2 p0 = g_dstPk[k], p1 = g_dstPk[k + 1];
        float a0 = g_alphaNR[(p0.y & 0xFFFFu) * RD + (p0.y >> 16)];
        float a1 = g_alphaNR[(p1.y & 0xFFFFu) * RD + (p1.y >> 16)];
        ull key0 = ((ull)__float_as_uint(a0) << 32) | (unsigned)(0xFFFFFFFFu - p0.x);
        ull key1 = ((ull)__float_as_uint(a1) << 32) | (unsigned)(0xFFFFFFFFu - p1.x);
        if (key0 >= th) {
            float4 xv = __ldg(&reinterpret_cast<const float4*>(x)[(size_t)(p0.y & 0xFFFFu) * 32 + l]);
            float4 rv = reinterpret_cast<const float4*>(g_rel)[(p0.y >> 16) * 32 + l];
            acc.x += a0 * (xv.x + rv.x); acc.y += a0 * (xv.y + rv.y);
            acc.z += a0 * (xv.z + rv.z); acc.w += a0 * (xv.w + rv.w);
        }
        if (key1 >= th) {
            float4 xv = __ldg(&reinterpret_cast<const float4*>(x)[(size_t)(p1.y & 0xFFFFu) * 32 + l]);
            float4 rv = reinterpret_cast<const float4*>(g_rel)[(p1.y >> 16) * 32 + l];
            acc.x += a1 * (xv.x + rv.x); acc.y += a1 * (xv.y + rv.y);
            acc.z += a1 * (xv.z + rv.z); acc.w += a1 * (xv.w + rv.w);
        }
    }
    if (k < end) {
        uint2 p0 = g_dstPk[k];
        float a0 = g_alphaNR[(p0.y & 0xFFFFu) * RD + (p0.y >> 16)];
        ull key0 = ((ull)__float_as_uint(a0) << 32) | (unsigned)(0xFFFFFFFFu - p0.x);
        if (key0 >= th) {
            float4 xv = __ldg(&reinterpret_cast<const float4*>(x)[(size_t)(p0.y & 0xFFFFu) * 32 + l]);
            float4 rv = reinterpret_cast<const float4*>(g_rel)[(p0.y >> 16) * 32 + l];
            acc.x += a0 * (xv.x + rv.x); acc.y += a0 * (xv.y + rv.y);
            acc.z += a0 * (xv.z + rv.z); acc.w += a0 * (xv.w + rv.w);
        }
    }
    reinterpret_cast<float4*>(g_scat)[(size_t)warp * 32 + l] = acc;
}

// ------ epi: f32x2 GEMM + LN + ELU + residual + next-iter alpha + coarse hist ------
__global__ __launch_bounds__(512) void k_epi(float* __restrict__ x,
                                             const float* __restrict__ lb,
                                             const float* __restrict__ lng,
                                             const float* __restrict__ lnb,
                                             int it) {
    __shared__ ull sWsP[2048];
    __shared__ ull sW2P[2048];
    __shared__ float4 sX[32][32];
    __shared__ float4 sS[32][32];
    __shared__ float sTr[BFDIM];
    __shared__ float sWa[BFDIM];
    __shared__ float racc[BFDIM];
    __shared__ float sLb[FD], sG[FD], sB[FD];
    __shared__ unsigned cHist[256];
    int tid = threadIdx.x;
    for (int i = tid; i < 2048; i += 512) {
        int j = i >> 5, lq = i & 31;
        sWsP[i] = fpack(g_wsumT[j * FD + lq], g_wsumT[j * FD + 32 + lq]);
        sW2P[i] = fpack(g_w2T[j * FD + lq], g_w2T[j * FD + 32 + lq]);
    }
    if (tid < BFDIM) {
        sTr[tid] = g_tr[tid];
        sWa[tid] = (it < 3) ? g_wa[(it + 1) * BFDIM + tid] : 0.f;
        racc[tid] = 0.f;
    }
    if (tid < FD) { sLb[tid] = lb[tid]; sG[tid] = lng[tid]; sB[tid] = lnb[tid]; }
    if (tid < 256) cHist[tid] = 0u;
    __syncthreads();
    int w = tid >> 5, l = tid & 31;
    float dnext = (it < 3) ? g_drel[(it + 1) * RD + l] : 0.f;
    int nbase = blockIdx.x * 32 + w * 2;
    int row0 = w * 2, row1 = w * 2 + 1;
#pragma unroll
    for (int nd = 0; nd < 2; ++nd) {
        int n = nbase + nd;
        sX[row0 + nd][l] = reinterpret_cast<const float4*>(x)[(size_t)n * 32 + l];
        sS[row0 + nd][l] = reinterpret_cast<const float4*>(g_scat)[(size_t)n * 32 + l];
    }
    __syncwarp();

    ull accP[2][2];
    accP[0][0] = accP[0][1] = accP[1][0] = accP[1][1] = 0ull;
    for (int jv = 0; jv < 16; ++jv) {
        float4 X0a = sX[row0][jv], X1a = sX[row0][16 + jv];
        float4 S0a = sS[row0][jv], S1a = sS[row0][16 + jv];
        float4 X0b = sX[row1][jv], X1b = sX[row1][16 + jv];
        float4 S0b = sS[row1][jv], S1b = sS[row1][16 + jv];
        const float* x0a = (const float*)&X0a; const float* x1a = (const float*)&X1a;
        const float* s0a = (const float*)&S0a; const float* s1a = (const float*)&S1a;
        const float* x0b = (const float*)&X0b; const float* x1b = (const float*)&X1b;
        const float* s0b = (const float*)&S0b; const float* s1b = (const float*)&S1b;
#pragma unroll
        for (int u = 0; u < 4; ++u) {
            int j = jv * 4 + u;
            ull wA = sWsP[j * 32 + l];
            ull wB = sW2P[j * 32 + l];
            ffma2(accP[0][0], wA, fdup(x0a[u]));
            ffma2(accP[0][0], wB, fdup(s0a[u]));
            ffma2(accP[0][1], wA, fdup(x1a[u]));
            ffma2(accP[0][1], wB, fdup(s1a[u]));
            ffma2(accP[1][0], wA, fdup(x0b[u]));
            ffma2(accP[1][0], wB, fdup(s0b[u]));
            ffma2(accP[1][1], wA, fdup(x1b[u]));
            ffma2(accP[1][1], wB, fdup(s1b[u]));
        }
    }

    const float* sXf = (const float*)sX;
#pragma unroll
    for (int nd = 0; nd < 2; ++nd) {
        int n = nbase + nd;
        int row = row0 + nd;
        float nxacc = 0.f;
#pragma unroll
        for (int b = 0; b < 2; ++b) {
            float a0, a1;
            funpack(accP[nd][b], a0, a1);
            float v0 = a0 + sLb[l] + sTr[b * 64 + l];
            float v1 = a1 + sLb[32 + l] + sTr[b * 64 + 32 + l];
            float s = v0 + v1;
            float q = v0 * v0 + v1 * v1;
#pragma unroll
            for (int o = 16; o; o >>= 1) {
                s += __shfl_xor_sync(0xffffffffu, s, o);
                q += __shfl_xor_sync(0xffffffffu, q, o);
            }
            float mu = s * (1.f / 64.f);
            float var = q * (1.f / 64.f) - mu * mu;
            float rs = rsqrtf(var + 1e-5f);
            v0 = (v0 - mu) * rs * sG[l] + sB[l];
            v1 = (v1 - mu) * rs * sG[32 + l] + sB[32 + l];
            v0 = v0 > 0.f ? v0 : expm1f(v0);
            v1 = v1 > 0.f ? v1 : expm1f(v1);
            float xn0 = v0 + sXf[row * BFDIM + b * 64 + l];
            float xn1 = v1 + sXf[row * BFDIM + b * 64 + 32 + l];
            x[(size_t)n * BFDIM + b * 64 + l] = xn0;
            x[(size_t)n * BFDIM + b * 64 + 32 + l] = xn1;
            if (it < 3) {
                nxacc += xn0 * sWa[b * 64 + l] + xn1 * sWa[b * 64 + 32 + l];
                atomicAdd(&racc[b * 64 + l], xn0);
                atomicAdd(&racc[b * 64 + 32 + l], xn1);
            }
        }
        if (it < 3) {
#pragma unroll
            for (int o = 16; o; o >>= 1) nxacc += __shfl_xor_sync(0xffffffffu, nxacc, o);
            // ---- next-iteration alpha for node n (lane = relation) ----
            unsigned c = g_cntNR[n * RD + l];
            bool valid = (c != 0u);
            unsigned vm = __ballot_sync(0xffffffffu, valid);
            if (vm == 0u) {
                g_alphaNR[n * RD + l] = 0.f;
            } else {
                float t = nxacc + dnext;
                t = t > 0.f ? t : 0.2f * t;
                float m = valid ? t : -CUDART_INF_F;
#pragma unroll
                for (int o = 16; o; o >>= 1) m = fmaxf(m, __shfl_xor_sync(0xffffffffu, m, o));
                float ex = valid ? expf(t - m) : 0.f;
                float cs = (float)c * ex;
#pragma unroll
                for (int o = 16; o; o >>= 1) cs += __shfl_xor_sync(0xffffffffu, cs, o);
                float a = ex * (1.f / (cs + 1e-16f));
                g_alphaNR[n * RD + l] = a;
                if (valid) atomicAdd(&cHist[__float_as_uint(a) >> 24], c);
            }
        }
    }
    __syncthreads();
    if (it < 3 && tid < BFDIM) atomicAdd(&g_rsum[tid], racc[tid]);
    if (it < 3 && tid < 256 && cHist[tid]) atomicAdd(&g_coarse[tid], cHist[tid]);
    if (it == 3) {
        int gid = blockIdx.x * 512 + tid;
        for (int i = gid; i < NN * RD; i += 625 * 512) g_cntNR[i] = 0u;
        if (gid < NN) { g_srcCnt[gid] = 0u; g_dstCnt[gid] = 0u; }
    }
}

// ---------------- launch ----------------
extern "C" void kernel_launch(void* const* d_in, const int* in_sizes, int n_in,
                              void* d_out, int out_size) {
    const int* ei  = (const int*)d_in[0];
    const int* ri  = (const int*)d_in[1];
    const float* bnd = (const float*)d_in[2];
    const float* qi  = (const float*)d_in[3];
    const float* rw  = (const float*)d_in[4];
    const float* rb  = (const float*)d_in[5];
    const float* lw  = (const float*)d_in[6];
    const float* lb  = (const float*)d_in[7];
    const float* trw = (const float*)d_in[8];
    const float* trb = (const float*)d_in[9];
    const float* Wm  = (const float*)d_in[10];
    const float* av  = (const float*)d_in[11];
    const float* lng = (const float*)d_in[12];
    const float* lnb = (const float*)d_in[13];
    float* x = (float*)d_out;

    k_prep1<<<34 + 1250, 256>>>(qi, rw, rb, Wm, av, lw, ei);
    k_csr_scan<<<1, 1024>>>();
    k_fill_init<<<1250 + 2500, 256>>>(ei, ri, bnd, x);

    for (int it = 0; it < NITER; ++it) {
        k_soft<<<SB, STH>>>(it, trw, trb);
        k_scatter<<<2500, 256>>>(x);
        k_epi<<<625, 512>>>(x, lb, lng, lnb, it);
    }
}